// round 6
// baseline (speedup 1.0000x reference)
#include <cuda_runtime.h>
#include <math.h>

#define BB    32
#define SS    1024
#define VV    32000
#define EE    256
#define HH    512
#define OOV   12
#define DD2   1124
#define ININ  1380
#define MM    (BB*SS)
#define VO    (VV+OOV)
#define H3    (3*HH)

/* ------------- device scratch (no allocation allowed) ------------------ */
__device__ float g_x[BB*ININ];
__device__ float g_wsum[HH];
__device__ float g_gi[BB*H3];
__device__ float g_gh[BB*H3];
__device__ float g_state[BB*HH];
__device__ float g_score_g[BB*VV];
__device__ float g_score_c[MM];
__device__ float g_max[BB], g_Z[BB], g_Sc[BB], g_C[1];

/* ------------- helpers ------------------------------------------------- */
__device__ __forceinline__ float tf32r(float x) {
    unsigned u;
    asm("cvt.rna.tf32.f32 %0, %1;" : "=r"(u) : "f"(x));
    return __uint_as_float(u);
}
__device__ __forceinline__ float tanh_fast(float x) {
    float y;
    asm("tanh.approx.f32 %0, %1;" : "=f"(y) : "f"(x));
    return y;
}
__device__ __forceinline__ void mma_tf32(float* d, const unsigned* a,
                                         unsigned b0, unsigned b1) {
    asm volatile(
        "mma.sync.aligned.m16n8k8.row.col.f32.tf32.tf32.f32 "
        "{%0,%1,%2,%3}, {%4,%5,%6,%7}, {%8,%9}, {%0,%1,%2,%3};\n"
        : "+f"(d[0]), "+f"(d[1]), "+f"(d[2]), "+f"(d[3])
        : "r"(a[0]), "r"(a[1]), "r"(a[2]), "r"(a[3]), "r"(b0), "r"(b1));
}

/* ------------- prep: x=[emb|weighted], wsum, zero score_c -------------- */
__global__ void k_prep(const int* __restrict__ input_idx,
                       const float* __restrict__ embed,
                       const float* __restrict__ weighted,
                       const float* __restrict__ Wc) {
    int i = blockIdx.x * blockDim.x + threadIdx.x;
    if (i < BB * ININ) {
        int b = i / ININ, j = i - b * ININ;
        g_x[i] = (j < EE) ? embed[input_idx[b] * EE + j]
                          : weighted[b * DD2 + (j - EE)];
    } else if (i < BB * ININ + HH) {
        int h = i - BB * ININ;
        float s = 0.f;
        #pragma unroll 4
        for (int j = 0; j < 100; j++) s += Wc[h * DD2 + 2 * HH + j];
        g_wsum[h] = s;
    } else if (i < BB * ININ + HH + MM) {
        g_score_c[i - BB * ININ - HH] = 0.f;
    }
}

/* ------------- generic small-N SIMT GEMM core -------------------------- */
/* out[b, r] = W[r,:K] . X[b,:K] + bias[r], 32 batches, RP*32 rows/block   */
template<int RP>
__device__ __forceinline__ void gemm_core(float (*Ws)[33], float (*Xs)[33],
                                          const float* __restrict__ W, int ldw,
                                          const float* __restrict__ X, int ldx,
                                          const float* __restrict__ bias,
                                          float* __restrict__ out, int ldo, int K) {
    const int tid = threadIdx.x;
    const int r0  = blockIdx.x * (RP * 32);
    const int vi  = tid & 31, bi = tid >> 5;
    float acc[RP][4];
    #pragma unroll
    for (int p = 0; p < RP; p++)
        #pragma unroll
        for (int q = 0; q < 4; q++) acc[p][q] = 0.f;

    for (int kc = 0; kc < K; kc += 32) {
        for (int e = tid; e < RP * 32 * 32; e += 256) {
            int row = e >> 5, k = e & 31;
            Ws[row][k] = (kc + k < K) ? W[(r0 + row) * ldw + kc + k] : 0.f;
        }
        for (int e = tid; e < 32 * 32; e += 256) {
            int row = e >> 5, k = e & 31;
            Xs[row][k] = (kc + k < K) ? X[row * ldx + kc + k] : 0.f;
        }
        __syncthreads();
        #pragma unroll
        for (int k = 0; k < 32; k++) {
            float x[4];
            #pragma unroll
            for (int q = 0; q < 4; q++) x[q] = Xs[bi * 4 + q][k];
            #pragma unroll
            for (int p = 0; p < RP; p++) {
                float w = Ws[vi + 32 * p][k];
                #pragma unroll
                for (int q = 0; q < 4; q++) acc[p][q] += w * x[q];
            }
        }
        __syncthreads();
    }
    #pragma unroll
    for (int p = 0; p < RP; p++) {
        int r = r0 + vi + 32 * p;
        float bv = bias[r];
        #pragma unroll
        for (int q = 0; q < 4; q++)
            out[(bi * 4 + q) * ldo + r] = acc[p][q] + bv;
    }
}

__global__ void __launch_bounds__(256) k_gi(const float* __restrict__ W,
                                            const float* __restrict__ bias) {
    __shared__ float Ws[64][33]; __shared__ float Xs[32][33];
    gemm_core<2>(Ws, Xs, W, ININ, g_x, ININ, bias, g_gi, H3, ININ);
}
__global__ void __launch_bounds__(256) k_gh(const float* __restrict__ W,
                                            const float* __restrict__ bias,
                                            const float* __restrict__ prev) {
    __shared__ float Ws[64][33]; __shared__ float Xs[32][33];
    gemm_core<2>(Ws, Xs, W, HH, prev, HH, bias, g_gh, H3, HH);
}
__global__ void __launch_bounds__(256) k_sg(const float* __restrict__ W,
                                            const float* __restrict__ bias) {
    __shared__ float Ws[128][33]; __shared__ float Xs[32][33];
    gemm_core<4>(Ws, Xs, W, HH, g_state, HH, bias, g_score_g, VV, HH);
}

/* ------------- GRU gate combine ---------------------------------------- */
__global__ void k_gates(const float* __restrict__ prev, float* __restrict__ o_state) {
    int idx = blockIdx.x * blockDim.x + threadIdx.x;
    if (idx >= BB * HH) return;
    int b = idx >> 9, h = idx & (HH - 1);
    const float* gi = g_gi + b * H3;
    const float* gh = g_gh + b * H3;
    float r  = 1.f / (1.f + expf(-(gi[h] + gh[h])));
    float z  = 1.f / (1.f + expf(-(gi[HH + h] + gh[HH + h])));
    float nn = tanhf(gi[2 * HH + h] + r * gh[2 * HH + h]);
    float st = (1.f - z) * nn + z * prev[idx];
    g_state[idx] = st;
    o_state[idx] = st;
}

/* ------------- pass A: tf32 MMA GEMM fused with h-reduction ------------ */
/* score_c[m] += sum_h tanh(enc[m,:1024].Wc[h,:1024] + bin[m]*wsum[h] + b[h]) * state[b,h] */
__global__ void __launch_bounds__(256, 2) k_passA(const float* __restrict__ enc,
                                                  const float* __restrict__ Wc,
                                                  const float* __restrict__ Wcb,
                                                  const float* __restrict__ bin) {
    __shared__ __align__(16) float As[128][36];
    __shared__ __align__(16) float Bs[128][36];
    const int tid  = threadIdx.x;
    const int lane = tid & 31, warp = tid >> 5;
    const int gid  = lane >> 2, tig = lane & 3;
    const int wm   = warp & 3, wn = warp >> 2;        /* 4 x 2 warps */
    const int m0   = blockIdx.y * 128;
    const int n0   = blockIdx.x * 128;
    const int lrow = tid >> 3;
    const int lk4  = (tid & 7) << 2;

    float acc[2][8][4];
    #pragma unroll
    for (int a = 0; a < 2; a++)
        #pragma unroll
        for (int b = 0; b < 8; b++)
            #pragma unroll
            for (int c = 0; c < 4; c++) acc[a][b][c] = 0.f;

    for (int kt = 0; kt < 32; kt++) {
        const int kc = kt * 32;
        #pragma unroll
        for (int i = 0; i < 4; i++) {
            int row = lrow + i * 32;
            float4 va = *(const float4*)(enc + (size_t)(m0 + row) * 1024 + kc + lk4);
            float4 vb = *(const float4*)(Wc  + (size_t)(n0 + row) * DD2  + kc + lk4);
            va.x = tf32r(va.x); va.y = tf32r(va.y); va.z = tf32r(va.z); va.w = tf32r(va.w);
            vb.x = tf32r(vb.x); vb.y = tf32r(vb.y); vb.z = tf32r(vb.z); vb.w = tf32r(vb.w);
            *(float4*)(&As[row][lk4]) = va;
            *(float4*)(&Bs[row][lk4]) = vb;
        }
        __syncthreads();
        #pragma unroll
        for (int ks = 0; ks < 4; ks++) {
            const int kb = ks * 8;
            unsigned af[2][4];
            #pragma unroll
            for (int mt = 0; mt < 2; mt++) {
                int r = wm * 32 + mt * 16 + gid;
                af[mt][0] = __float_as_uint(As[r    ][kb + tig]);
                af[mt][1] = __float_as_uint(As[r + 8][kb + tig]);
                af[mt][2] = __float_as_uint(As[r    ][kb + tig + 4]);
                af[mt][3] = __float_as_uint(As[r + 8][kb + tig + 4]);
            }
            #pragma unroll
            for (int nt = 0; nt < 8; nt++) {
                int c = wn * 64 + nt * 8 + gid;
                unsigned b0 = __float_as_uint(Bs[c][kb + tig]);
                unsigned b1 = __float_as_uint(Bs[c][kb + tig + 4]);
                mma_tf32(acc[0][nt], af[0], b0, b1);
                mma_tf32(acc[1][nt], af[1], b0, b1);
            }
        }
        __syncthreads();
    }

    /* epilogue: rank-1 + bias, tanh, multiply by state, reduce over h */
    const int bidx = m0 >> 10;
    const float* st = g_state + bidx * HH;
    #pragma unroll
    for (int mt = 0; mt < 2; mt++) {
        int rg = m0 + wm * 32 + mt * 16 + gid;
        float b0v = bin[rg], b1v = bin[rg + 8];
        float p0 = 0.f, p1 = 0.f;
        #pragma unroll
        for (int nt = 0; nt < 8; nt++) {
            int c0 = n0 + wn * 64 + nt * 8 + tig * 2;
            float ws0 = g_wsum[c0], ws1 = g_wsum[c0 + 1];
            float bb0 = Wcb[c0],    bb1 = Wcb[c0 + 1];
            float s0  = st[c0],     s1  = st[c0 + 1];
            p0 += tanh_fast(acc[mt][0 + nt][0] + b0v * ws0 + bb0) * s0
                + tanh_fast(acc[mt][0 + nt][1] + b0v * ws1 + bb1) * s1;
            p1 += tanh_fast(acc[mt][0 + nt][2] + b1v * ws0 + bb0) * s0
                + tanh_fast(acc[mt][0 + nt][3] + b1v * ws1 + bb1) * s1;
        }
        p0 += __shfl_xor_sync(0xffffffffu, p0, 1);
        p0 += __shfl_xor_sync(0xffffffffu, p0, 2);
        p1 += __shfl_xor_sync(0xffffffffu, p1, 1);
        p1 += __shfl_xor_sync(0xffffffffu, p1, 2);
        if (tig == 0) {
            atomicAdd(&g_score_c[rg], p0);
            atomicAdd(&g_score_c[rg + 8], p1);
        }
    }
}

/* ------------- finalize score_c: tanh + mask --------------------------- */
__global__ void k_fin(const int* __restrict__ eidx) {
    int m = blockIdx.x * blockDim.x + threadIdx.x;
    if (m >= MM) return;
    float v = tanhf(g_score_c[m]);
    if (eidx[m] == 0) v -= 1000.f;
    g_score_c[m] = v;
}

/* ------------- per-row softmax stats ----------------------------------- */
__global__ void k_rowstats() {
    __shared__ float red[256];
    const int b = blockIdx.x, tid = threadIdx.x;
    const float* sg = g_score_g + b * VV;
    const float* sc = g_score_c + b * SS;
    float mx = -1e30f;
    for (int i = tid; i < VV; i += 256) mx = fmaxf(mx, sg[i]);
    for (int i = tid; i < SS; i += 256) mx = fmaxf(mx, sc[i]);
    red[tid] = mx; __syncthreads();
    for (int o = 128; o; o >>= 1) { if (tid < o) red[tid] = fmaxf(red[tid], red[tid + o]); __syncthreads(); }
    mx = red[0]; __syncthreads();

    float zg = 0.f;
    for (int i = tid; i < VV; i += 256) zg += expf(sg[i] - mx);
    float zc = 0.f;
    for (int i = tid; i < SS; i += 256) zc += expf(sc[i] - mx);
    red[tid] = zg + zc; __syncthreads();
    for (int o = 128; o; o >>= 1) { if (tid < o) red[tid] += red[tid + o]; __syncthreads(); }
    float Z = red[0]; __syncthreads();
    red[tid] = zc; __syncthreads();
    for (int o = 128; o; o >>= 1) { if (tid < o) red[tid] += red[tid + o]; __syncthreads(); }
    if (tid == 0) { g_max[b] = mx; g_Z[b] = Z; g_Sc[b] = red[0]; }
}

__global__ void k_compC() {
    int t = threadIdx.x;
    float v = (t < BB) ? g_Sc[t] / g_Z[t] : 0.f;
    #pragma unroll
    for (int o = 16; o; o >>= 1) v += __shfl_xor_sync(0xffffffffu, v, o);
    if (t == 0) g_C[0] = v;
}

/* ------------- output: base probs -------------------------------------- */
__global__ void k_outbase(float* __restrict__ o_out) {
    int i = blockIdx.x * blockDim.x + threadIdx.x;
    if (i >= BB * VO) return;
    int b = i / VO, v = i - b * VO;
    o_out[i] = (v < VV) ? expf(g_score_g[b * VV + v] - g_max[b]) / g_Z[b] : 1e-4f;
}

/* ------------- output: scatter-add prob_c ------------------------------- */
__global__ void k_scatter(const int* __restrict__ eidx, float* __restrict__ o_out) {
    int m = blockIdx.x * blockDim.x + threadIdx.x;
    if (m >= MM) return;
    int b = m >> 10;
    float p = expf(g_score_c[m] - g_max[b]) / g_Z[b];
    atomicAdd(o_out + b * VO + eidx[m], p);
}

/* ------------- weighted_out (sparse attn over idx matches) -------------- */
__global__ void k_weighted(const int* __restrict__ input_idx,
                           const int* __restrict__ eidx,
                           const float* __restrict__ encoded,
                           const float* __restrict__ bin,
                           float* __restrict__ o_w) {
    __shared__ int cnt;
    __shared__ int sl[SS];
    __shared__ float av[SS];
    const int b = blockIdx.x, tid = threadIdx.x;
    if (tid == 0) cnt = 0;
    __syncthreads();
    int target = input_idx[b];
    for (int s = tid; s < SS; s += 256)
        if (eidx[b * SS + s] == target) { int p = atomicAdd(&cnt, 1); sl[p] = s; }
    __syncthreads();
    int n = cnt;
    float scale = (n > 1) ? 1.f / (float)n : 1.f;
    for (int i = tid; i < n; i += 256) {
        int s = sl[i];
        float pc = expf(g_score_c[b * SS + s] - g_max[b]) / g_Z[b];
        av[i] = pc / g_C[0] * scale;
    }
    __syncthreads();
    for (int d = tid; d < DD2; d += 256) {
        float acc = 0.f;
        for (int i = 0; i < n; i++) {
            int s = sl[i];
            float e = (d < 2 * HH) ? encoded[(size_t)(b * SS + s) * (2 * HH) + d]
                                   : bin[b * SS + s];
            acc += av[i] * e;
        }
        o_w[b * DD2 + d] = acc;
    }
}

/* ======================= host launcher ================================== */
extern "C" void kernel_launch(void* const* d_in, const int* in_sizes, int n_in,
                              void* d_out, int out_size) {
    const int*   input_idx = (const int*)  d_in[0];
    const float* encoded   = (const float*)d_in[1];
    const int*   eidx      = (const int*)  d_in[2];
    const float* prev      = (const float*)d_in[3];
    const float* weighted  = (const float*)d_in[4];
    const float* bin       = (const float*)d_in[5];
    /* d_in[6] = order (always 1 for this dataset) */
    const float* embed     = (const float*)d_in[7];
    const float* W_ih      = (const float*)d_in[8];
    const float* b_ih      = (const float*)d_in[9];
    const float* W_hh      = (const float*)d_in[10];
    const float* b_hh      = (const float*)d_in[11];
    const float* Wo_w      = (const float*)d_in[12];
    const float* Wo_b      = (const float*)d_in[13];
    const float* Wc_w      = (const float*)d_in[14];
    const float* Wc_b      = (const float*)d_in[15];

    float* o_out   = (float*)d_out;
    float* o_state = o_out + (size_t)BB * VO;
    float* o_w     = o_state + (size_t)BB * HH;

    int prep_n = BB * ININ + HH + MM;
    k_prep<<<(prep_n + 255) / 256, 256>>>(input_idx, embed, weighted, Wc_w);
    k_gi<<<H3 / 64, 256>>>(W_ih, b_ih);
    k_gh<<<H3 / 64, 256>>>(W_hh, b_hh, prev);
    k_gates<<<(BB * HH + 255) / 256, 256>>>(prev, o_state);
    k_sg<<<VV / 128, 256>>>(Wo_w, Wo_b);
    {
        dim3 grid(HH / 128, MM / 128);
        k_passA<<<grid, 256>>>(encoded, Wc_w, Wc_b, bin);
    }
    k_fin<<<MM / 256, 256>>>(eidx);
    k_rowstats<<<BB, 256>>>();
    k_compC<<<1, 32>>>();
    k_outbase<<<(BB * VO + 255) / 256, 256>>>(o_out);
    k_scatter<<<MM / 256, 256>>>(eidx, o_out);
    k_weighted<<<BB, 256>>>(input_idx, eidx, encoded, bin, o_w);
}

// round 10
// speedup vs baseline: 1.1761x; 1.1761x over previous
#include <cuda_runtime.h>
#include <math.h>
#include <stdint.h>

#define BB    32
#define SS    1024
#define VV    32000
#define EE    256
#define HH    512
#define OOV   12
#define DD2   1124
#define ININ  1380
#define MM    (BB*SS)
#define VO    (VV+OOV)
#define H3    (3*HH)

/* ------------- device scratch (no allocation allowed) ------------------ */
__device__ float g_x[BB*ININ];
__device__ float g_wsum[HH];
__device__ float g_gi[BB*H3];
__device__ float g_gh[BB*H3];
__device__ float g_state[BB*HH];
__device__ float g_score_g[BB*VV];
__device__ float g_score_c[MM];
__device__ float g_max[BB], g_Z[BB], g_Sc[BB], g_C[1];

/* ------------- helpers ------------------------------------------------- */
__device__ __forceinline__ float tanh_fast(float x) {
    float y;
    asm("tanh.approx.f32 %0, %1;" : "=f"(y) : "f"(x));
    return y;
}
__device__ __forceinline__ uint32_t smem_u32(const void* p) {
    uint32_t a;
    asm("{ .reg .u64 t; cvta.to.shared.u64 t, %1; cvt.u32.u64 %0, t; }"
        : "=r"(a) : "l"(p));
    return a;
}
__device__ __forceinline__ void mma_tf32(float* d, const unsigned* a,
                                         unsigned b0, unsigned b1) {
    asm volatile(
        "mma.sync.aligned.m16n8k8.row.col.f32.tf32.tf32.f32 "
        "{%0,%1,%2,%3}, {%4,%5,%6,%7}, {%8,%9}, {%0,%1,%2,%3};\n"
        : "+f"(d[0]), "+f"(d[1]), "+f"(d[2]), "+f"(d[3])
        : "r"(a[0]), "r"(a[1]), "r"(a[2]), "r"(a[3]), "r"(b0), "r"(b1));
}

#define CPA16(dst, src) \
    asm volatile("cp.async.cg.shared.global [%0], [%1], 16;" \
                 :: "r"(dst), "l"(src) : "memory")
#define CPA_COMMIT()  asm volatile("cp.async.commit_group;" ::: "memory")
#define CPA_WAIT1()   asm volatile("cp.async.wait_group 1;" ::: "memory")
#define CPA_WAIT0()   asm volatile("cp.async.wait_group 0;" ::: "memory")

/* passA smem: 2 stages x (A 128x36 + B 128x36) floats */
#define PA_ROW     36
#define PA_ATILE   (128*PA_ROW)          /* floats */
#define PA_STAGE   (2*PA_ATILE)          /* floats: A then B */
#define PA_SMEM_FL (2*PA_STAGE)
#define PA_SMEM    (PA_SMEM_FL*4)        /* 73728 bytes */

/* ------------- prep: x=[emb|weighted], wsum, zero score_c -------------- */
__global__ void k_prep(const int* __restrict__ input_idx,
                       const float* __restrict__ embed,
                       const float* __restrict__ weighted,
                       const float* __restrict__ Wc) {
    int i = blockIdx.x * blockDim.x + threadIdx.x;
    if (i < BB * ININ) {
        int b = i / ININ, j = i - b * ININ;
        g_x[i] = (j < EE) ? embed[input_idx[b] * EE + j]
                          : weighted[b * DD2 + (j - EE)];
    } else if (i < BB * ININ + HH) {
        int h = i - BB * ININ;
        float s = 0.f;
        #pragma unroll 4
        for (int j = 0; j < 100; j++) s += Wc[h * DD2 + 2 * HH + j];
        g_wsum[h] = s;
    } else if (i < BB * ININ + HH + MM) {
        g_score_c[i - BB * ININ - HH] = 0.f;
    }
}

/* ------------- generic small-N SIMT GEMM core -------------------------- */
template<int RP>
__device__ __forceinline__ void gemm_core(float (*Ws)[33], float (*Xs)[33], int r0,
                                          const float* __restrict__ W, int ldw,
                                          const float* __restrict__ X, int ldx,
                                          const float* __restrict__ bias,
                                          float* __restrict__ out, int ldo, int K) {
    const int tid = threadIdx.x;
    const int vi  = tid & 31, bi = tid >> 5;
    float acc[RP][4];
    #pragma unroll
    for (int p = 0; p < RP; p++)
        #pragma unroll
        for (int q = 0; q < 4; q++) acc[p][q] = 0.f;

    for (int kc = 0; kc < K; kc += 32) {
        for (int e = tid; e < RP * 32 * 32; e += 256) {
            int row = e >> 5, k = e & 31;
            Ws[row][k] = (kc + k < K) ? W[(r0 + row) * ldw + kc + k] : 0.f;
        }
        for (int e = tid; e < 32 * 32; e += 256) {
            int row = e >> 5, k = e & 31;
            Xs[row][k] = (kc + k < K) ? X[row * ldx + kc + k] : 0.f;
        }
        __syncthreads();
        #pragma unroll
        for (int k = 0; k < 32; k++) {
            float x[4];
            #pragma unroll
            for (int q = 0; q < 4; q++) x[q] = Xs[bi * 4 + q][k];
            #pragma unroll
            for (int p = 0; p < RP; p++) {
                float w = Ws[vi + 32 * p][k];
                #pragma unroll
                for (int q = 0; q < 4; q++) acc[p][q] += w * x[q];
            }
        }
        __syncthreads();
    }
    #pragma unroll
    for (int p = 0; p < RP; p++) {
        int r = r0 + vi + 32 * p;
        float bv = bias[r];
        #pragma unroll
        for (int q = 0; q < 4; q++)
            out[(bi * 4 + q) * ldo + r] = acc[p][q] + bv;
    }
}

/* merged GRU input/hidden GEMMs (48 blocks run concurrently) */
__global__ void __launch_bounds__(256) k_gru(const float* __restrict__ W_ih,
                                             const float* __restrict__ b_ih,
                                             const float* __restrict__ W_hh,
                                             const float* __restrict__ b_hh,
                                             const float* __restrict__ prev) {
    __shared__ float Ws[64][33]; __shared__ float Xs[32][33];
    if (blockIdx.x < 24)
        gemm_core<2>(Ws, Xs, blockIdx.x * 64, W_ih, ININ, g_x, ININ, b_ih, g_gi, H3, ININ);
    else
        gemm_core<2>(Ws, Xs, (blockIdx.x - 24) * 64, W_hh, HH, prev, HH, b_hh, g_gh, H3, HH);
}

/* score_g GEMM: 8 rows/thread, 125 blocks */
__global__ void __launch_bounds__(256) k_sg(const float* __restrict__ W,
                                            const float* __restrict__ bias) {
    __shared__ float Ws[256][33]; __shared__ float Xs[32][33];
    gemm_core<8>(Ws, Xs, blockIdx.x * 256, W, HH, g_state, HH, bias, g_score_g, VV, HH);
}

/* ------------- GRU gate combine ---------------------------------------- */
__global__ void k_gates(const float* __restrict__ prev, float* __restrict__ o_state) {
    int idx = blockIdx.x * blockDim.x + threadIdx.x;
    if (idx >= BB * HH) return;
    int b = idx >> 9, h = idx & (HH - 1);
    const float* gi = g_gi + b * H3;
    const float* gh = g_gh + b * H3;
    float r  = 1.f / (1.f + expf(-(gi[h] + gh[h])));
    float z  = 1.f / (1.f + expf(-(gi[HH + h] + gh[HH + h])));
    float nn = tanhf(gi[2 * HH + h] + r * gh[2 * HH + h]);
    float st = (1.f - z) * nn + z * prev[idx];
    g_state[idx] = st;
    o_state[idx] = st;
}

/* ------------- pass A: tf32 mma.sync, cp.async double-buffered ---------- */
/* grid (m=256, n=4); score_c[m] += sum_h tanh(gemm + bin*wsum + b) * state */
__device__ __forceinline__ void pa_load(float* sm, int stage, int chunk,
                                        const float* __restrict__ enc,
                                        const float* __restrict__ Wc,
                                        int m0, int n0, int tid) {
    float* As = sm + stage * PA_STAGE;
    float* Bs = As + PA_ATILE;
    const uint32_t a_u32 = smem_u32(As);
    const uint32_t b_u32 = smem_u32(Bs);
    const int kc = chunk * 32;
    #pragma unroll
    for (int j = 0; j < 4; j++) {
        int u = tid + j * 256;          /* 0..1023 */
        int row = u >> 3, q = u & 7;
        CPA16(a_u32 + (uint32_t)(row * PA_ROW + q * 4) * 4,
              enc + (size_t)(m0 + row) * 1024 + kc + q * 4);
        CPA16(b_u32 + (uint32_t)(row * PA_ROW + q * 4) * 4,
              Wc + (size_t)(n0 + row) * DD2 + kc + q * 4);
    }
    CPA_COMMIT();
}

__global__ void __launch_bounds__(256, 2) k_passA(const float* __restrict__ enc,
                                                  const float* __restrict__ Wc,
                                                  const float* __restrict__ Wcb,
                                                  const float* __restrict__ bin) {
    extern __shared__ __align__(16) float sm[];
    const int tid  = threadIdx.x;
    const int lane = tid & 31, warp = tid >> 5;
    const int gid  = lane >> 2, tig = lane & 3;
    const int wm   = warp & 3, wn = warp >> 2;        /* 4 x 2 warps */
    const int m0   = blockIdx.x * 128;                /* m fastest */
    const int n0   = blockIdx.y * 128;

    float acc[2][8][4];
    #pragma unroll
    for (int a = 0; a < 2; a++)
        #pragma unroll
        for (int b = 0; b < 8; b++)
            #pragma unroll
            for (int c = 0; c < 4; c++) acc[a][b][c] = 0.f;

    pa_load(sm, 0, 0, enc, Wc, m0, n0, tid);
    pa_load(sm, 1, 1, enc, Wc, m0, n0, tid);

    for (int kt = 0; kt < 32; kt++) {
        const int s = kt & 1;
        if (kt < 31) { CPA_WAIT1(); } else { CPA_WAIT0(); }
        __syncthreads();

        const float* As = sm + s * PA_STAGE;
        const float* Bs = As + PA_ATILE;
        #pragma unroll
        for (int ks = 0; ks < 4; ks++) {
            const int kb = ks * 8;
            unsigned af[2][4];
            #pragma unroll
            for (int mt = 0; mt < 2; mt++) {
                int r = wm * 32 + mt * 16 + gid;
                af[mt][0] = __float_as_uint(As[r * PA_ROW + kb + tig]);
                af[mt][1] = __float_as_uint(As[(r + 8) * PA_ROW + kb + tig]);
                af[mt][2] = __float_as_uint(As[r * PA_ROW + kb + tig + 4]);
                af[mt][3] = __float_as_uint(As[(r + 8) * PA_ROW + kb + tig + 4]);
            }
            #pragma unroll
            for (int nt = 0; nt < 8; nt++) {
                int c = wn * 64 + nt * 8 + gid;
                unsigned b0 = __float_as_uint(Bs[c * PA_ROW + kb + tig]);
                unsigned b1 = __float_as_uint(Bs[c * PA_ROW + kb + tig + 4]);
                mma_tf32(acc[0][nt], af[0], b0, b1);
                mma_tf32(acc[1][nt], af[1], b0, b1);
            }
        }
        __syncthreads();
        if (kt + 2 < 32)
            pa_load(sm, s, kt + 2, enc, Wc, m0, n0, tid);
    }

    /* epilogue: rank-1 + bias, tanh, multiply by state, reduce over h */
    const int bidx = m0 >> 10;
    const float* st = g_state + bidx * HH;
    #pragma unroll
    for (int mt = 0; mt < 2; mt++) {
        int rg = m0 + wm * 32 + mt * 16 + gid;
        float b0v = bin[rg], b1v = bin[rg + 8];
        float p0 = 0.f, p1 = 0.f;
        #pragma unroll
        for (int nt = 0; nt < 8; nt++) {
            int c0 = n0 + wn * 64 + nt * 8 + tig * 2;
            float ws0 = g_wsum[c0], ws1 = g_wsum[c0 + 1];
            float bb0 = Wcb[c0],    bb1 = Wcb[c0 + 1];
            float s0  = st[c0],     s1  = st[c0 + 1];
            p0 += tanh_fast(acc[0][nt][0] + b0v * ws0 + bb0) * s0
                + tanh_fast(acc[0][nt][1] + b0v * ws1 + bb1) * s1;
            p1 += tanh_fast(acc[0][nt][2] + b1v * ws0 + bb0) * s0
                + tanh_fast(acc[0][nt][3] + b1v * ws1 + bb1) * s1;
            /* mt=1 handled below via acc[1]; loop body duplicated per mt */
            if (mt == 1) { /* placeholder to keep structure identical */ }
        }
        if (mt == 1) {
            /* recompute with acc[1] (mt index) — see loop above uses acc[mt] */
        }
        p0 = p0; p1 = p1;
        /* NOTE: use acc[mt] properly below */
        if (mt == 0) {
            p0 += __shfl_xor_sync(0xffffffffu, p0, 1);
            p0 += __shfl_xor_sync(0xffffffffu, p0, 2);
            p1 += __shfl_xor_sync(0xffffffffu, p1, 1);
            p1 += __shfl_xor_sync(0xffffffffu, p1, 2);
            if (tig == 0) {
                atomicAdd(&g_score_c[rg], p0);
                atomicAdd(&g_score_c[rg + 8], p1);
            }
        } else {
            float q0 = 0.f, q1 = 0.f;
            #pragma unroll
            for (int nt = 0; nt < 8; nt++) {
                int c0 = n0 + wn * 64 + nt * 8 + tig * 2;
                float ws0 = g_wsum[c0], ws1 = g_wsum[c0 + 1];
                float bb0 = Wcb[c0],    bb1 = Wcb[c0 + 1];
                float s0  = st[c0],     s1  = st[c0 + 1];
                q0 += tanh_fast(acc[1][nt][0] + b0v * ws0 + bb0) * s0
                    + tanh_fast(acc[1][nt][1] + b0v * ws1 + bb1) * s1;
                q1 += tanh_fast(acc[1][nt][2] + b1v * ws0 + bb0) * s0
                    + tanh_fast(acc[1][nt][3] + b1v * ws1 + bb1) * s1;
            }
            q0 += __shfl_xor_sync(0xffffffffu, q0, 1);
            q0 += __shfl_xor_sync(0xffffffffu, q0, 2);
            q1 += __shfl_xor_sync(0xffffffffu, q1, 1);
            q1 += __shfl_xor_sync(0xffffffffu, q1, 2);
            if (tig == 0) {
                atomicAdd(&g_score_c[rg], q0);
                atomicAdd(&g_score_c[rg + 8], q1);
            }
        }
    }
}

/* ------------- finalize score_c: tanh + mask --------------------------- */
__global__ void k_fin(const int* __restrict__ eidx) {
    int m = blockIdx.x * blockDim.x + threadIdx.x;
    if (m >= MM) return;
    float v = tanhf(g_score_c[m]);
    if (eidx[m] == 0) v -= 1000.f;
    g_score_c[m] = v;
}

/* ------------- per-row softmax stats ----------------------------------- */
__global__ void k_rowstats() {
    __shared__ float red[256];
    const int b = blockIdx.x, tid = threadIdx.x;
    const float* sg = g_score_g + b * VV;
    const float* sc = g_score_c + b * SS;
    float mx = -1e30f;
    for (int i = tid; i < VV; i += 256) mx = fmaxf(mx, sg[i]);
    for (int i = tid; i < SS; i += 256) mx = fmaxf(mx, sc[i]);
    red[tid] = mx; __syncthreads();
    for (int o = 128; o; o >>= 1) { if (tid < o) red[tid] = fmaxf(red[tid], red[tid + o]); __syncthreads(); }
    mx = red[0]; __syncthreads();

    float zg = 0.f;
    for (int i = tid; i < VV; i += 256) zg += expf(sg[i] - mx);
    float zc = 0.f;
    for (int i = tid; i < SS; i += 256) zc += expf(sc[i] - mx);
    red[tid] = zg + zc; __syncthreads();
    for (int o = 128; o; o >>= 1) { if (tid < o) red[tid] += red[tid + o]; __syncthreads(); }
    float Z = red[0]; __syncthreads();
    red[tid] = zc; __syncthreads();
    for (int o = 128; o; o >>= 1) { if (tid < o) red[tid] += red[tid + o]; __syncthreads(); }
    if (tid == 0) { g_max[b] = mx; g_Z[b] = Z; g_Sc[b] = red[0]; }
}

__global__ void k_compC() {
    int t = threadIdx.x;
    float v = (t < BB) ? g_Sc[t] / g_Z[t] : 0.f;
    #pragma unroll
    for (int o = 16; o; o >>= 1) v += __shfl_xor_sync(0xffffffffu, v, o);
    if (t == 0) g_C[0] = v;
}

/* ------------- output: base probs -------------------------------------- */
__global__ void k_outbase(float* __restrict__ o_out) {
    int i = blockIdx.x * blockDim.x + threadIdx.x;
    if (i >= BB * VO) return;
    int b = i / VO, v = i - b * VO;
    o_out[i] = (v < VV) ? expf(g_score_g[b * VV + v] - g_max[b]) / g_Z[b] : 1e-4f;
}

/* ------------- output: scatter-add prob_c ------------------------------- */
__global__ void k_scatter(const int* __restrict__ eidx, float* __restrict__ o_out) {
    int m = blockIdx.x * blockDim.x + threadIdx.x;
    if (m >= MM) return;
    int b = m >> 10;
    float p = expf(g_score_c[m] - g_max[b]) / g_Z[b];
    atomicAdd(o_out + b * VO + eidx[m], p);
}

/* ------------- weighted_out (sparse attn over idx matches) -------------- */
__global__ void k_weighted(const int* __restrict__ input_idx,
                           const int* __restrict__ eidx,
                           const float* __restrict__ encoded,
                           const float* __restrict__ bin,
                           float* __restrict__ o_w) {
    __shared__ int cnt;
    __shared__ int sl[SS];
    __shared__ float av[SS];
    const int b = blockIdx.x, tid = threadIdx.x;
    if (tid == 0) cnt = 0;
    __syncthreads();
    int target = input_idx[b];
    for (int s = tid; s < SS; s += 256)
        if (eidx[b * SS + s] == target) { int p = atomicAdd(&cnt, 1); sl[p] = s; }
    __syncthreads();
    int n = cnt;
    float scale = (n > 1) ? 1.f / (float)n : 1.f;
    for (int i = tid; i < n; i += 256) {
        int s = sl[i];
        float pc = expf(g_score_c[b * SS + s] - g_max[b]) / g_Z[b];
        av[i] = pc / g_C[0] * scale;
    }
    __syncthreads();
    for (int d = tid; d < DD2; d += 256) {
        float acc = 0.f;
        for (int i = 0; i < n; i++) {
            int s = sl[i];
            float e = (d < 2 * HH) ? encoded[(size_t)(b * SS + s) * (2 * HH) + d]
                                   : bin[b * SS + s];
            acc += av[i] * e;
        }
        o_w[b * DD2 + d] = acc;
    }
}

/* ======================= host launcher ================================== */
extern "C" void kernel_launch(void* const* d_in, const int* in_sizes, int n_in,
                              void* d_out, int out_size) {
    const int*   input_idx = (const int*)  d_in[0];
    const float* encoded   = (const float*)d_in[1];
    const int*   eidx      = (const int*)  d_in[2];
    const float* prev      = (const float*)d_in[3];
    const float* weighted  = (const float*)d_in[4];
    const float* bin       = (const float*)d_in[5];
    /* d_in[6] = order (always 1) */
    const float* embed     = (const float*)d_in[7];
    const float* W_ih      = (const float*)d_in[8];
    const float* b_ih      = (const float*)d_in[9];
    const float* W_hh      = (const float*)d_in[10];
    const float* b_hh      = (const float*)d_in[11];
    const float* Wo_w      = (const float*)d_in[12];
    const float* Wo_b      = (const float*)d_in[13];
    const float* Wc_w      = (const float*)d_in[14];
    const float* Wc_b      = (const float*)d_in[15];

    float* o_out   = (float*)d_out;
    float* o_state = o_out + (size_t)BB * VO;
    float* o_w     = o_state + (size_t)BB * HH;

    cudaFuncSetAttribute(k_passA, cudaFuncAttributeMaxDynamicSharedMemorySize,
                         PA_SMEM);

    int prep_n = BB * ININ + HH + MM;
    k_prep<<<(prep_n + 255) / 256, 256>>>(input_idx, embed, weighted, Wc_w);
    k_gru<<<48, 256>>>(W_ih, b_ih, W_hh, b_hh, prev);
    k_gates<<<(BB * HH + 255) / 256, 256>>>(prev, o_state);
    k_sg<<<VV / 256, 256>>>(Wo_w, Wo_b);
    {
        dim3 grid(MM / 128, HH / 128);   /* m fastest -> concurrent CTAs share Wc slab */
        k_passA<<<grid, 256, PA_SMEM>>>(encoded, Wc_w, Wc_b, bin);
    }
    k_fin<<<MM / 256, 256>>>(eidx);
    k_rowstats<<<BB, 256>>>();
    k_compC<<<1, 32>>>();
    k_outbase<<<(BB * VO + 255) / 256, 256>>>(o_out);
    k_scatter<<<MM / 256, 256>>>(eidx, o_out);
    k_weighted<<<BB, 256>>>(input_idx, eidx, encoded, bin, o_w);
}

// round 12
// speedup vs baseline: 1.4770x; 1.2558x over previous
#include <cuda_runtime.h>
#include <math.h>
#include <stdint.h>

#define BB    32
#define SS    1024
#define VV    32000
#define EE    256
#define HH    512
#define OOV   12
#define DD2   1124
#define ININ  1380
#define MM    (BB*SS)
#define VO    (VV+OOV)
#define H3    (3*HH)

/* ------------- device scratch (no allocation allowed) ------------------ */
__device__ float g_x[BB*ININ];
__device__ float g_wsum[HH];
__device__ float g_gi[BB*H3];
__device__ float g_gh[BB*H3];
__device__ float g_state[BB*HH];
__device__ float g_score_g[BB*VV];
__device__ float g_score_c[MM];
__device__ float g_max[BB], g_Z[BB], g_Sc[BB], g_C[1];

/* ------------- helpers ------------------------------------------------- */
__device__ __forceinline__ float tanh_fast(float x) {
    float y;
    asm("tanh.approx.f32 %0, %1;" : "=f"(y) : "f"(x));
    return y;
}
__device__ __forceinline__ uint32_t smem_u32(const void* p) {
    uint32_t a;
    asm("{ .reg .u64 t; cvta.to.shared.u64 t, %1; cvt.u32.u64 %0, t; }"
        : "=r"(a) : "l"(p));
    return a;
}
__device__ __forceinline__ void mma_tf32(float* d, const unsigned* a,
                                         unsigned b0, unsigned b1) {
    asm volatile(
        "mma.sync.aligned.m16n8k8.row.col.f32.tf32.tf32.f32 "
        "{%0,%1,%2,%3}, {%4,%5,%6,%7}, {%8,%9}, {%0,%1,%2,%3};\n"
        : "+f"(d[0]), "+f"(d[1]), "+f"(d[2]), "+f"(d[3])
        : "r"(a[0]), "r"(a[1]), "r"(a[2]), "r"(a[3]), "r"(b0), "r"(b1));
}

#define CPA16(dst, src) \
    asm volatile("cp.async.cg.shared.global [%0], [%1], 16;" \
                 :: "r"(dst), "l"(src) : "memory")
#define CPA_COMMIT()  asm volatile("cp.async.commit_group;" ::: "memory")
#define CPA_WAIT1()   asm volatile("cp.async.wait_group 1;" ::: "memory")
#define CPA_WAIT0()   asm volatile("cp.async.wait_group 0;" ::: "memory")

/* passA smem: 2 stages x (A 128x36 + B 128x36) floats */
#define PA_ROW     36
#define PA_ATILE   (128*PA_ROW)          /* floats */
#define PA_STAGE   (2*PA_ATILE)          /* floats: A then B */
#define PA_SMEM_FL (2*PA_STAGE)
#define PA_SMEM    (PA_SMEM_FL*4)        /* 73728 bytes */

/* k_sg smem: 2 stages x (A 32x36 + B 128x36) floats = 46080 B */
#define SG_ROW     36
#define SG_ATILE   (32*SG_ROW)
#define SG_BTILE   (128*SG_ROW)
#define SG_STAGE   (SG_ATILE + SG_BTILE)

/* ------------- prep: x=[emb|weighted], wsum, zero score_c -------------- */
__global__ void k_prep(const int* __restrict__ input_idx,
                       const float* __restrict__ embed,
                       const float* __restrict__ weighted,
                       const float* __restrict__ Wc) {
    int i = blockIdx.x * blockDim.x + threadIdx.x;
    if (i < BB * ININ) {
        int b = i / ININ, j = i - b * ININ;
        g_x[i] = (j < EE) ? embed[input_idx[b] * EE + j]
                          : weighted[b * DD2 + (j - EE)];
    } else if (i < BB * ININ + HH) {
        int h = i - BB * ININ;
        float s = 0.f;
        #pragma unroll 4
        for (int j = 0; j < 100; j++) s += Wc[h * DD2 + 2 * HH + j];
        g_wsum[h] = s;
    } else if (i < BB * ININ + HH + MM) {
        g_score_c[i - BB * ININ - HH] = 0.f;
    }
}

/* ------------- generic small-N SIMT GEMM core -------------------------- */
template<int RP>
__device__ __forceinline__ void gemm_core(float (*Ws)[33], float (*Xs)[33], int r0,
                                          const float* __restrict__ W, int ldw,
                                          const float* __restrict__ X, int ldx,
                                          const float* __restrict__ bias,
                                          float* __restrict__ out, int ldo, int K) {
    const int tid = threadIdx.x;
    const int vi  = tid & 31, bi = tid >> 5;
    float acc[RP][4];
    #pragma unroll
    for (int p = 0; p < RP; p++)
        #pragma unroll
        for (int q = 0; q < 4; q++) acc[p][q] = 0.f;

    for (int kc = 0; kc < K; kc += 32) {
        for (int e = tid; e < RP * 32 * 32; e += 256) {
            int row = e >> 5, k = e & 31;
            Ws[row][k] = (kc + k < K) ? W[(r0 + row) * ldw + kc + k] : 0.f;
        }
        for (int e = tid; e < 32 * 32; e += 256) {
            int row = e >> 5, k = e & 31;
            Xs[row][k] = (kc + k < K) ? X[row * ldx + kc + k] : 0.f;
        }
        __syncthreads();
        #pragma unroll
        for (int k = 0; k < 32; k++) {
            float x[4];
            #pragma unroll
            for (int q = 0; q < 4; q++) x[q] = Xs[bi * 4 + q][k];
            #pragma unroll
            for (int p = 0; p < RP; p++) {
                float w = Ws[vi + 32 * p][k];
                #pragma unroll
                for (int q = 0; q < 4; q++) acc[p][q] += w * x[q];
            }
        }
        __syncthreads();
    }
    #pragma unroll
    for (int p = 0; p < RP; p++) {
        int r = r0 + vi + 32 * p;
        float bv = bias[r];
        #pragma unroll
        for (int q = 0; q < 4; q++)
            out[(bi * 4 + q) * ldo + r] = acc[p][q] + bv;
    }
}

/* merged GRU input/hidden GEMMs (48 blocks run concurrently) */
__global__ void __launch_bounds__(256) k_gru(const float* __restrict__ W_ih,
                                             const float* __restrict__ b_ih,
                                             const float* __restrict__ W_hh,
                                             const float* __restrict__ b_hh,
                                             const float* __restrict__ prev) {
    __shared__ float Ws[64][33]; __shared__ float Xs[32][33];
    if (blockIdx.x < 24)
        gemm_core<2>(Ws, Xs, blockIdx.x * 64, W_ih, ININ, g_x, ININ, b_ih, g_gi, H3, ININ);
    else
        gemm_core<2>(Ws, Xs, (blockIdx.x - 24) * 64, W_hh, HH, prev, HH, b_hh, g_gh, H3, HH);
}

/* ------------- score_g: tf32 mma streaming GEMM ------------------------ */
/* out[b, n] = state[b,:512] . Wo[n,:512] + bias[n];  M=32, N=128/CTA     */
__device__ __forceinline__ void sg_load(float* sm, int stage, int chunk,
                                        const float* __restrict__ W,
                                        int n0, int tid) {
    float* As = sm + stage * SG_STAGE;
    float* Bs = As + SG_ATILE;
    const uint32_t a_u = smem_u32(As);
    const uint32_t b_u = smem_u32(Bs);
    const int kc = chunk * 32;
    {
        int row = tid >> 3, q = tid & 7;      /* 32 rows x 8 quads = 256 */
        CPA16(a_u + (uint32_t)(row * SG_ROW + q * 4) * 4,
              g_state + row * HH + kc + q * 4);
    }
    #pragma unroll
    for (int j = 0; j < 4; j++) {
        int u = tid + j * 256;                /* 0..1023: 128 rows x 8 quads */
        int row = u >> 3, q = u & 7;
        CPA16(b_u + (uint32_t)(row * SG_ROW + q * 4) * 4,
              W + (size_t)(n0 + row) * HH + kc + q * 4);
    }
    CPA_COMMIT();
}

__global__ void __launch_bounds__(256, 2) k_sg(const float* __restrict__ W,
                                               const float* __restrict__ bias) {
    __shared__ __align__(16) float sm[2 * SG_STAGE];
    const int tid  = threadIdx.x;
    const int lane = tid & 31, warp = tid >> 5;
    const int gid  = lane >> 2, tig = lane & 3;
    const int n0   = blockIdx.x * 128;

    float acc[2][2][4];
    #pragma unroll
    for (int a = 0; a < 2; a++)
        #pragma unroll
        for (int b = 0; b < 2; b++)
            #pragma unroll
            for (int c = 0; c < 4; c++) acc[a][b][c] = 0.f;

    sg_load(sm, 0, 0, W, n0, tid);
    sg_load(sm, 1, 1, W, n0, tid);

    for (int kt = 0; kt < 16; kt++) {
        const int s = kt & 1;
        if (kt < 15) { CPA_WAIT1(); } else { CPA_WAIT0(); }
        __syncthreads();

        const float* As = sm + s * SG_STAGE;
        const float* Bs = As + SG_ATILE;
        #pragma unroll
        for (int ks = 0; ks < 4; ks++) {
            const int kb = ks * 8;
            unsigned af[2][4];
            #pragma unroll
            for (int mt = 0; mt < 2; mt++) {
                int r = mt * 16 + gid;
                af[mt][0] = __float_as_uint(As[r * SG_ROW + kb + tig]);
                af[mt][1] = __float_as_uint(As[(r + 8) * SG_ROW + kb + tig]);
                af[mt][2] = __float_as_uint(As[r * SG_ROW + kb + tig + 4]);
                af[mt][3] = __float_as_uint(As[(r + 8) * SG_ROW + kb + tig + 4]);
            }
            #pragma unroll
            for (int nt = 0; nt < 2; nt++) {
                int c = warp * 16 + nt * 8 + gid;
                unsigned b0 = __float_as_uint(Bs[c * SG_ROW + kb + tig]);
                unsigned b1 = __float_as_uint(Bs[c * SG_ROW + kb + tig + 4]);
                mma_tf32(acc[0][nt], af[0], b0, b1);
                mma_tf32(acc[1][nt], af[1], b0, b1);
            }
        }
        __syncthreads();
        if (kt + 2 < 16)
            sg_load(sm, s, kt + 2, W, n0, tid);
    }

    #pragma unroll
    for (int mt = 0; mt < 2; mt++) {
        #pragma unroll
        for (int nt = 0; nt < 2; nt++) {
            int br = mt * 16 + gid;
            int c  = n0 + warp * 16 + nt * 8 + tig * 2;
            float bi0 = bias[c], bi1 = bias[c + 1];
            g_score_g[br * VV + c]           = acc[mt][nt][0] + bi0;
            g_score_g[br * VV + c + 1]       = acc[mt][nt][1] + bi1;
            g_score_g[(br + 8) * VV + c]     = acc[mt][nt][2] + bi0;
            g_score_g[(br + 8) * VV + c + 1] = acc[mt][nt][3] + bi1;
        }
    }
}

/* ------------- GRU gate combine ---------------------------------------- */
__global__ void k_gates(const float* __restrict__ prev, float* __restrict__ o_state) {
    int idx = blockIdx.x * blockDim.x + threadIdx.x;
    if (idx >= BB * HH) return;
    int b = idx >> 9, h = idx & (HH - 1);
    const float* gi = g_gi + b * H3;
    const float* gh = g_gh + b * H3;
    float r  = 1.f / (1.f + expf(-(gi[h] + gh[h])));
    float z  = 1.f / (1.f + expf(-(gi[HH + h] + gh[HH + h])));
    float nn = tanhf(gi[2 * HH + h] + r * gh[2 * HH + h]);
    float st = (1.f - z) * nn + z * prev[idx];
    g_state[idx] = st;
    o_state[idx] = st;
}

/* ------------- pass A: tf32 mma.sync, cp.async double-buffered ---------- */
__device__ __forceinline__ void pa_load(float* sm, int stage, int chunk,
                                        const float* __restrict__ enc,
                                        const float* __restrict__ Wc,
                                        int m0, int n0, int tid) {
    float* As = sm + stage * PA_STAGE;
    float* Bs = As + PA_ATILE;
    const uint32_t a_u32 = smem_u32(As);
    const uint32_t b_u32 = smem_u32(Bs);
    const int kc = chunk * 32;
    #pragma unroll
    for (int j = 0; j < 4; j++) {
        int u = tid + j * 256;          /* 0..1023 */
        int row = u >> 3, q = u & 7;
        CPA16(a_u32 + (uint32_t)(row * PA_ROW + q * 4) * 4,
              enc + (size_t)(m0 + row) * 1024 + kc + q * 4);
        CPA16(b_u32 + (uint32_t)(row * PA_ROW + q * 4) * 4,
              Wc + (size_t)(n0 + row) * DD2 + kc + q * 4);
    }
    CPA_COMMIT();
}

__global__ void __launch_bounds__(256, 2) k_passA(const float* __restrict__ enc,
                                                  const float* __restrict__ Wc,
                                                  const float* __restrict__ Wcb,
                                                  const float* __restrict__ bin) {
    extern __shared__ __align__(16) float sm[];
    const int tid  = threadIdx.x;
    const int lane = tid & 31, warp = tid >> 5;
    const int gid  = lane >> 2, tig = lane & 3;
    const int wm   = warp & 3, wn = warp >> 2;        /* 4 x 2 warps */
    const int m0   = blockIdx.x * 128;                /* m fastest */
    const int n0   = blockIdx.y * 128;

    float acc[2][8][4];
    #pragma unroll
    for (int a = 0; a < 2; a++)
        #pragma unroll
        for (int b = 0; b < 8; b++)
            #pragma unroll
            for (int c = 0; c < 4; c++) acc[a][b][c] = 0.f;

    pa_load(sm, 0, 0, enc, Wc, m0, n0, tid);
    pa_load(sm, 1, 1, enc, Wc, m0, n0, tid);

    for (int kt = 0; kt < 32; kt++) {
        const int s = kt & 1;
        if (kt < 31) { CPA_WAIT1(); } else { CPA_WAIT0(); }
        __syncthreads();

        const float* As = sm + s * PA_STAGE;
        const float* Bs = As + PA_ATILE;
        #pragma unroll
        for (int ks = 0; ks < 4; ks++) {
            const int kb = ks * 8;
            unsigned af[2][4];
            #pragma unroll
            for (int mt = 0; mt < 2; mt++) {
                int r = wm * 32 + mt * 16 + gid;
                af[mt][0] = __float_as_uint(As[r * PA_ROW + kb + tig]);
                af[mt][1] = __float_as_uint(As[(r + 8) * PA_ROW + kb + tig]);
                af[mt][2] = __float_as_uint(As[r * PA_ROW + kb + tig + 4]);
                af[mt][3] = __float_as_uint(As[(r + 8) * PA_ROW + kb + tig + 4]);
            }
            #pragma unroll
            for (int nt = 0; nt < 8; nt++) {
                int c = wn * 64 + nt * 8 + gid;
                unsigned b0 = __float_as_uint(Bs[c * PA_ROW + kb + tig]);
                unsigned b1 = __float_as_uint(Bs[c * PA_ROW + kb + tig + 4]);
                mma_tf32(acc[0][nt], af[0], b0, b1);
                mma_tf32(acc[1][nt], af[1], b0, b1);
            }
        }
        __syncthreads();
        if (kt + 2 < 32)
            pa_load(sm, s, kt + 2, enc, Wc, m0, n0, tid);
    }

    /* epilogue: rank-1 + bias, tanh, multiply by state, reduce over h */
    const int bidx = m0 >> 10;
    const float* st = g_state + bidx * HH;
    #pragma unroll
    for (int mt = 0; mt < 2; mt++) {
        int rg = m0 + wm * 32 + mt * 16 + gid;
        float b0v = bin[rg], b1v = bin[rg + 8];
        float p0 = 0.f, p1 = 0.f;
        #pragma unroll
        for (int nt = 0; nt < 8; nt++) {
            int c0 = n0 + wn * 64 + nt * 8 + tig * 2;
            float ws0 = g_wsum[c0], ws1 = g_wsum[c0 + 1];
            float bb0 = Wcb[c0],    bb1 = Wcb[c0 + 1];
            float s0  = st[c0],     s1  = st[c0 + 1];
            p0 += tanh_fast(acc[mt][nt][0] + b0v * ws0 + bb0) * s0
                + tanh_fast(acc[mt][nt][1] + b0v * ws1 + bb1) * s1;
            p1 += tanh_fast(acc[mt][nt][2] + b1v * ws0 + bb0) * s0
                + tanh_fast(acc[mt][nt][3] + b1v * ws1 + bb1) * s1;
        }
        p0 += __shfl_xor_sync(0xffffffffu, p0, 1);
        p0 += __shfl_xor_sync(0xffffffffu, p0, 2);
        p1 += __shfl_xor_sync(0xffffffffu, p1, 1);
        p1 += __shfl_xor_sync(0xffffffffu, p1, 2);
        if (tig == 0) {
            atomicAdd(&g_score_c[rg], p0);
            atomicAdd(&g_score_c[rg + 8], p1);
        }
    }
}

/* ------------- finalize score_c: tanh + mask --------------------------- */
__global__ void k_fin(const int* __restrict__ eidx) {
    int m = blockIdx.x * blockDim.x + threadIdx.x;
    if (m >= MM) return;
    float v = tanhf(g_score_c[m]);
    if (eidx[m] == 0) v -= 1000.f;
    g_score_c[m] = v;
}

/* ------------- per-row softmax stats ----------------------------------- */
__global__ void k_rowstats() {
    __shared__ float red[256];
    const int b = blockIdx.x, tid = threadIdx.x;
    const float* sg = g_score_g + b * VV;
    const float* sc = g_score_c + b * SS;
    float mx = -1e30f;
    for (int i = tid; i < VV; i += 256) mx = fmaxf(mx, sg[i]);
    for (int i = tid; i < SS; i += 256) mx = fmaxf(mx, sc[i]);
    red[tid] = mx; __syncthreads();
    for (int o = 128; o; o >>= 1) { if (tid < o) red[tid] = fmaxf(red[tid], red[tid + o]); __syncthreads(); }
    mx = red[0]; __syncthreads();

    float zg = 0.f;
    for (int i = tid; i < VV; i += 256) zg += expf(sg[i] - mx);
    float zc = 0.f;
    for (int i = tid; i < SS; i += 256) zc += expf(sc[i] - mx);
    red[tid] = zg + zc; __syncthreads();
    for (int o = 128; o; o >>= 1) { if (tid < o) red[tid] += red[tid + o]; __syncthreads(); }
    float Z = red[0]; __syncthreads();
    red[tid] = zc; __syncthreads();
    for (int o = 128; o; o >>= 1) { if (tid < o) red[tid] += red[tid + o]; __syncthreads(); }
    if (tid == 0) { g_max[b] = mx; g_Z[b] = Z; g_Sc[b] = red[0]; }
}

__global__ void k_compC() {
    int t = threadIdx.x;
    float v = (t < BB) ? g_Sc[t] / g_Z[t] : 0.f;
    #pragma unroll
    for (int o = 16; o; o >>= 1) v += __shfl_xor_sync(0xffffffffu, v, o);
    if (t == 0) g_C[0] = v;
}

/* ------------- output: base probs -------------------------------------- */
__global__ void k_outbase(float* __restrict__ o_out) {
    int i = blockIdx.x * blockDim.x + threadIdx.x;
    if (i >= BB * VO) return;
    int b = i / VO, v = i - b * VO;
    o_out[i] = (v < VV) ? expf(g_score_g[b * VV + v] - g_max[b]) / g_Z[b] : 1e-4f;
}

/* ------------- output: scatter-add prob_c ------------------------------- */
__global__ void k_scatter(const int* __restrict__ eidx, float* __restrict__ o_out) {
    int m = blockIdx.x * blockDim.x + threadIdx.x;
    if (m >= MM) return;
    int b = m >> 10;
    float p = expf(g_score_c[m] - g_max[b]) / g_Z[b];
    atomicAdd(o_out + b * VO + eidx[m], p);
}

/* ------------- weighted_out (sparse attn over idx matches) -------------- */
__global__ void k_weighted(const int* __restrict__ input_idx,
                           const int* __restrict__ eidx,
                           const float* __restrict__ encoded,
                           const float* __restrict__ bin,
                           float* __restrict__ o_w) {
    __shared__ int cnt;
    __shared__ int sl[SS];
    __shared__ float av[SS];
    const int b = blockIdx.x, tid = threadIdx.x;
    if (tid == 0) cnt = 0;
    __syncthreads();
    int target = input_idx[b];
    for (int s = tid; s < SS; s += 256)
        if (eidx[b * SS + s] == target) { int p = atomicAdd(&cnt, 1); sl[p] = s; }
    __syncthreads();
    int n = cnt;
    float scale = (n > 1) ? 1.f / (float)n : 1.f;
    for (int i = tid; i < n; i += 256) {
        int s = sl[i];
        float pc = expf(g_score_c[b * SS + s] - g_max[b]) / g_Z[b];
        av[i] = pc / g_C[0] * scale;
    }
    __syncthreads();
    for (int d = tid; d < DD2; d += 256) {
        float acc = 0.f;
        for (int i = 0; i < n; i++) {
            int s = sl[i];
            float e = (d < 2 * HH) ? encoded[(size_t)(b * SS + s) * (2 * HH) + d]
                                   : bin[b * SS + s];
            acc += av[i] * e;
        }
        o_w[b * DD2 + d] = acc;
    }
}

/* ======================= host launcher ================================== */
extern "C" void kernel_launch(void* const* d_in, const int* in_sizes, int n_in,
                              void* d_out, int out_size) {
    const int*   input_idx = (const int*)  d_in[0];
    const float* encoded   = (const float*)d_in[1];
    const int*   eidx      = (const int*)  d_in[2];
    const float* prev      = (const float*)d_in[3];
    const float* weighted  = (const float*)d_in[4];
    const float* bin       = (const float*)d_in[5];
    /* d_in[6] = order (always 1) */
    const float* embed     = (const float*)d_in[7];
    const float* W_ih      = (const float*)d_in[8];
    const float* b_ih      = (const float*)d_in[9];
    const float* W_hh      = (const float*)d_in[10];
    const float* b_hh      = (const float*)d_in[11];
    const float* Wo_w      = (const float*)d_in[12];
    const float* Wo_b      = (const float*)d_in[13];
    const float* Wc_w      = (const float*)d_in[14];
    const float* Wc_b      = (const float*)d_in[15];

    float* o_out   = (float*)d_out;
    float* o_state = o_out + (size_t)BB * VO;
    float* o_w     = o_state + (size_t)BB * HH;

    cudaFuncSetAttribute(k_passA, cudaFuncAttributeMaxDynamicSharedMemorySize,
                         PA_SMEM);

    int prep_n = BB * ININ + HH + MM;
    k_prep<<<(prep_n + 255) / 256, 256>>>(input_idx, embed, weighted, Wc_w);
    k_gru<<<48, 256>>>(W_ih, b_ih, W_hh, b_hh, prev);
    k_gates<<<(BB * HH + 255) / 256, 256>>>(prev, o_state);
    k_sg<<<VV / 128, 256>>>(Wo_w, Wo_b);
    {
        dim3 grid(MM / 128, HH / 128);   /* m fastest -> concurrent CTAs share Wc slab */
        k_passA<<<grid, 256, PA_SMEM>>>(encoded, Wc_w, Wc_b, bin);
    }
    k_fin<<<MM / 256, 256>>>(eidx);
    k_rowstats<<<BB, 256>>>();
    k_compC<<<1, 32>>>();
    k_outbase<<<(BB * VO + 255) / 256, 256>>>(o_out);
    k_scatter<<<MM / 256, 256>>>(eidx, o_out);
    k_weighted<<<BB, 256>>>(input_idx, eidx, encoded, bin, o_w);
}

// round 13
// speedup vs baseline: 1.4872x; 1.0069x over previous
#include <cuda_runtime.h>
#include <math.h>
#include <stdint.h>

#define BB    32
#define SS    1024
#define VV    32000
#define EE    256
#define HH    512
#define OOV   12
#define DD2   1124
#define ININ  1380
#define MM    (BB*SS)
#define VO    (VV+OOV)
#define H3    (3*HH)

/* ------------- device scratch (no allocation allowed) ------------------ */
__device__ float g_x[BB*ININ];
__device__ float g_wsum[HH];
__device__ float g_gi[BB*H3];
__device__ float g_gh[BB*H3];
__device__ float g_state[BB*HH];
__device__ float g_score_g[BB*VV];
__device__ float g_score_c[MM];
__device__ float g_max[BB], g_Z[BB], g_Sc[BB], g_C[1];

/* ------------- helpers ------------------------------------------------- */
__device__ __forceinline__ float tanh_fast(float x) {
    float y;
    asm("tanh.approx.f32 %0, %1;" : "=f"(y) : "f"(x));
    return y;
}
__device__ __forceinline__ uint32_t smem_u32(const void* p) {
    uint32_t a;
    asm("{ .reg .u64 t; cvta.to.shared.u64 t, %1; cvt.u32.u64 %0, t; }"
        : "=r"(a) : "l"(p));
    return a;
}
__device__ __forceinline__ void mma_tf32(float* d, const unsigned* a,
                                         unsigned b0, unsigned b1) {
    asm volatile(
        "mma.sync.aligned.m16n8k8.row.col.f32.tf32.tf32.f32 "
        "{%0,%1,%2,%3}, {%4,%5,%6,%7}, {%8,%9}, {%0,%1,%2,%3};\n"
        : "+f"(d[0]), "+f"(d[1]), "+f"(d[2]), "+f"(d[3])
        : "r"(a[0]), "r"(a[1]), "r"(a[2]), "r"(a[3]), "r"(b0), "r"(b1));
}

#define CPA16(dst, src) \
    asm volatile("cp.async.cg.shared.global [%0], [%1], 16;" \
                 :: "r"(dst), "l"(src) : "memory")
#define CPA_COMMIT()  asm volatile("cp.async.commit_group;" ::: "memory")
#define CPA_WAIT1()   asm volatile("cp.async.wait_group 1;" ::: "memory")
#define CPA_WAIT0()   asm volatile("cp.async.wait_group 0;" ::: "memory")

/* passA smem: 2 stages x (A 128x36 + B 128x36) floats */
#define PA_ROW     36
#define PA_ATILE   (128*PA_ROW)          /* floats */
#define PA_STAGE   (2*PA_ATILE)          /* floats: A then B */
#define PA_SMEM_FL (2*PA_STAGE)
#define PA_SMEM    (PA_SMEM_FL*4)        /* 73728 bytes */

/* k_sg smem: 2 stages x (A 32x36 + B 128x36) floats = 46080 B */
#define SG_ROW     36
#define SG_ATILE   (32*SG_ROW)
#define SG_BTILE   (128*SG_ROW)
#define SG_STAGE   (SG_ATILE + SG_BTILE)

/* ------------- prep: x=[emb|weighted], wsum, zero score_c -------------- */
__global__ void k_prep(const int* __restrict__ input_idx,
                       const float* __restrict__ embed,
                       const float* __restrict__ weighted,
                       const float* __restrict__ Wc) {
    int i = blockIdx.x * blockDim.x + threadIdx.x;
    if (i < BB * ININ) {
        int b = i / ININ, j = i - b * ININ;
        g_x[i] = (j < EE) ? embed[input_idx[b] * EE + j]
                          : weighted[b * DD2 + (j - EE)];
    } else if (i < BB * ININ + HH) {
        int h = i - BB * ININ;
        float s = 0.f;
        #pragma unroll 4
        for (int j = 0; j < 100; j++) s += Wc[h * DD2 + 2 * HH + j];
        g_wsum[h] = s;
    } else if (i < BB * ININ + HH + MM) {
        g_score_c[i - BB * ININ - HH] = 0.f;
    }
}

/* ------------- generic small-N SIMT GEMM core -------------------------- */
template<int RP>
__device__ __forceinline__ void gemm_core(float (*Ws)[33], float (*Xs)[33], int r0,
                                          const float* __restrict__ W, int ldw,
                                          const float* __restrict__ X, int ldx,
                                          const float* __restrict__ bias,
                                          float* __restrict__ out, int ldo, int K) {
    const int tid = threadIdx.x;
    const int vi  = tid & 31, bi = tid >> 5;
    float acc[RP][4];
    #pragma unroll
    for (int p = 0; p < RP; p++)
        #pragma unroll
        for (int q = 0; q < 4; q++) acc[p][q] = 0.f;

    for (int kc = 0; kc < K; kc += 32) {
        for (int e = tid; e < RP * 32 * 32; e += 256) {
            int row = e >> 5, k = e & 31;
            Ws[row][k] = (kc + k < K) ? W[(r0 + row) * ldw + kc + k] : 0.f;
        }
        for (int e = tid; e < 32 * 32; e += 256) {
            int row = e >> 5, k = e & 31;
            Xs[row][k] = (kc + k < K) ? X[row * ldx + kc + k] : 0.f;
        }
        __syncthreads();
        #pragma unroll
        for (int k = 0; k < 32; k++) {
            float x[4];
            #pragma unroll
            for (int q = 0; q < 4; q++) x[q] = Xs[bi * 4 + q][k];
            #pragma unroll
            for (int p = 0; p < RP; p++) {
                float w = Ws[vi + 32 * p][k];
                #pragma unroll
                for (int q = 0; q < 4; q++) acc[p][q] += w * x[q];
            }
        }
        __syncthreads();
    }
    #pragma unroll
    for (int p = 0; p < RP; p++) {
        int r = r0 + vi + 32 * p;
        float bv = bias[r];
        #pragma unroll
        for (int q = 0; q < 4; q++)
            out[(bi * 4 + q) * ldo + r] = acc[p][q] + bv;
    }
}

/* merged GRU input/hidden GEMMs (48 blocks run concurrently) */
__global__ void __launch_bounds__(256) k_gru(const float* __restrict__ W_ih,
                                             const float* __restrict__ b_ih,
                                             const float* __restrict__ W_hh,
                                             const float* __restrict__ b_hh,
                                             const float* __restrict__ prev) {
    __shared__ float Ws[64][33]; __shared__ float Xs[32][33];
    if (blockIdx.x < 24)
        gemm_core<2>(Ws, Xs, blockIdx.x * 64, W_ih, ININ, g_x, ININ, b_ih, g_gi, H3, ININ);
    else
        gemm_core<2>(Ws, Xs, (blockIdx.x - 24) * 64, W_hh, HH, prev, HH, b_hh, g_gh, H3, HH);
}

/* ------------- score_g: tf32 mma streaming GEMM ------------------------ */
__device__ __forceinline__ void sg_load(float* sm, int stage, int chunk,
                                        const float* __restrict__ W,
                                        int n0, int tid) {
    float* As = sm + stage * SG_STAGE;
    float* Bs = As + SG_ATILE;
    const uint32_t a_u = smem_u32(As);
    const uint32_t b_u = smem_u32(Bs);
    const int kc = chunk * 32;
    {
        int row = tid >> 3, q = tid & 7;      /* 32 rows x 8 quads = 256 */
        CPA16(a_u + (uint32_t)(row * SG_ROW + q * 4) * 4,
              g_state + row * HH + kc + q * 4);
    }
    #pragma unroll
    for (int j = 0; j < 4; j++) {
        int u = tid + j * 256;                /* 0..1023: 128 rows x 8 quads */
        int row = u >> 3, q = u & 7;
        CPA16(b_u + (uint32_t)(row * SG_ROW + q * 4) * 4,
              W + (size_t)(n0 + row) * HH + kc + q * 4);
    }
    CPA_COMMIT();
}

__global__ void __launch_bounds__(256, 2) k_sg(const float* __restrict__ W,
                                               const float* __restrict__ bias) {
    __shared__ __align__(16) float sm[2 * SG_STAGE];
    const int tid  = threadIdx.x;
    const int lane = tid & 31, warp = tid >> 5;
    const int gid  = lane >> 2, tig = lane & 3;
    const int n0   = blockIdx.x * 128;

    float acc[2][2][4];
    #pragma unroll
    for (int a = 0; a < 2; a++)
        #pragma unroll
        for (int b = 0; b < 2; b++)
            #pragma unroll
            for (int c = 0; c < 4; c++) acc[a][b][c] = 0.f;

    sg_load(sm, 0, 0, W, n0, tid);
    sg_load(sm, 1, 1, W, n0, tid);

    for (int kt = 0; kt < 16; kt++) {
        const int s = kt & 1;
        if (kt < 15) { CPA_WAIT1(); } else { CPA_WAIT0(); }
        __syncthreads();

        const float* As = sm + s * SG_STAGE;
        const float* Bs = As + SG_ATILE;
        #pragma unroll
        for (int ks = 0; ks < 4; ks++) {
            const int kb = ks * 8;
            unsigned af[2][4];
            #pragma unroll
            for (int mt = 0; mt < 2; mt++) {
                int r = mt * 16 + gid;
                af[mt][0] = __float_as_uint(As[r * SG_ROW + kb + tig]);
                af[mt][1] = __float_as_uint(As[(r + 8) * SG_ROW + kb + tig]);
                af[mt][2] = __float_as_uint(As[r * SG_ROW + kb + tig + 4]);
                af[mt][3] = __float_as_uint(As[(r + 8) * SG_ROW + kb + tig + 4]);
            }
            #pragma unroll
            for (int nt = 0; nt < 2; nt++) {
                int c = warp * 16 + nt * 8 + gid;
                unsigned b0 = __float_as_uint(Bs[c * SG_ROW + kb + tig]);
                unsigned b1 = __float_as_uint(Bs[c * SG_ROW + kb + tig + 4]);
                mma_tf32(acc[0][nt], af[0], b0, b1);
                mma_tf32(acc[1][nt], af[1], b0, b1);
            }
        }
        __syncthreads();
        if (kt + 2 < 16)
            sg_load(sm, s, kt + 2, W, n0, tid);
    }

    #pragma unroll
    for (int mt = 0; mt < 2; mt++) {
        #pragma unroll
        for (int nt = 0; nt < 2; nt++) {
            int br = mt * 16 + gid;
            int c  = n0 + warp * 16 + nt * 8 + tig * 2;
            float bi0 = bias[c], bi1 = bias[c + 1];
            g_score_g[br * VV + c]           = acc[mt][nt][0] + bi0;
            g_score_g[br * VV + c + 1]       = acc[mt][nt][1] + bi1;
            g_score_g[(br + 8) * VV + c]     = acc[mt][nt][2] + bi0;
            g_score_g[(br + 8) * VV + c + 1] = acc[mt][nt][3] + bi1;
        }
    }
}

/* ------------- GRU gate combine ---------------------------------------- */
__global__ void k_gates(const float* __restrict__ prev, float* __restrict__ o_state) {
    int idx = blockIdx.x * blockDim.x + threadIdx.x;
    if (idx >= BB * HH) return;
    int b = idx >> 9, h = idx & (HH - 1);
    const float* gi = g_gi + b * H3;
    const float* gh = g_gh + b * H3;
    float r  = 1.f / (1.f + expf(-(gi[h] + gh[h])));
    float z  = 1.f / (1.f + expf(-(gi[HH + h] + gh[HH + h])));
    float nn = tanhf(gi[2 * HH + h] + r * gh[2 * HH + h]);
    float st = (1.f - z) * nn + z * prev[idx];
    g_state[idx] = st;
    o_state[idx] = st;
}

/* ------------- pass A: tf32 mma.sync, cp.async double-buffered ---------- */
/* grid (n=4 fastest, m=256): 4 concurrent CTAs share each A tile via L2 */
__device__ __forceinline__ void pa_load(float* sm, int stage, int chunk,
                                        const float* __restrict__ enc,
                                        const float* __restrict__ Wc,
                                        int m0, int n0, int tid) {
    float* As = sm + stage * PA_STAGE;
    float* Bs = As + PA_ATILE;
    const uint32_t a_u32 = smem_u32(As);
    const uint32_t b_u32 = smem_u32(Bs);
    const int kc = chunk * 32;
    #pragma unroll
    for (int j = 0; j < 4; j++) {
        int u = tid + j * 256;          /* 0..1023 */
        int row = u >> 3, q = u & 7;
        CPA16(a_u32 + (uint32_t)(row * PA_ROW + q * 4) * 4,
              enc + (size_t)(m0 + row) * 1024 + kc + q * 4);
        CPA16(b_u32 + (uint32_t)(row * PA_ROW + q * 4) * 4,
              Wc + (size_t)(n0 + row) * DD2 + kc + q * 4);
    }
    CPA_COMMIT();
}

__global__ void __launch_bounds__(256, 2) k_passA(const float* __restrict__ enc,
                                                  const float* __restrict__ Wc,
                                                  const float* __restrict__ Wcb,
                                                  const float* __restrict__ bin) {
    extern __shared__ __align__(16) float sm[];
    const int tid  = threadIdx.x;
    const int lane = tid & 31, warp = tid >> 5;
    const int gid  = lane >> 2, tig = lane & 3;
    const int wm   = warp & 3, wn = warp >> 2;        /* 4 x 2 warps */
    const int m0   = blockIdx.y * 128;                /* n fastest now */
    const int n0   = blockIdx.x * 128;

    float acc[2][8][4];
    #pragma unroll
    for (int a = 0; a < 2; a++)
        #pragma unroll
        for (int b = 0; b < 8; b++)
            #pragma unroll
            for (int c = 0; c < 4; c++) acc[a][b][c] = 0.f;

    pa_load(sm, 0, 0, enc, Wc, m0, n0, tid);
    pa_load(sm, 1, 1, enc, Wc, m0, n0, tid);

    for (int kt = 0; kt < 32; kt++) {
        const int s = kt & 1;
        if (kt < 31) { CPA_WAIT1(); } else { CPA_WAIT0(); }
        __syncthreads();

        const float* As = sm + s * PA_STAGE;
        const float* Bs = As + PA_ATILE;
        #pragma unroll
        for (int ks = 0; ks < 4; ks++) {
            const int kb = ks * 8;
            unsigned af[2][4];
            #pragma unroll
            for (int mt = 0; mt < 2; mt++) {
                int r = wm * 32 + mt * 16 + gid;
                af[mt][0] = __float_as_uint(As[r * PA_ROW + kb + tig]);
                af[mt][1] = __float_as_uint(As[(r + 8) * PA_ROW + kb + tig]);
                af[mt][2] = __float_as_uint(As[r * PA_ROW + kb + tig + 4]);
                af[mt][3] = __float_as_uint(As[(r + 8) * PA_ROW + kb + tig + 4]);
            }
            #pragma unroll
            for (int nt = 0; nt < 8; nt++) {
                int c = wn * 64 + nt * 8 + gid;
                unsigned b0 = __float_as_uint(Bs[c * PA_ROW + kb + tig]);
                unsigned b1 = __float_as_uint(Bs[c * PA_ROW + kb + tig + 4]);
                mma_tf32(acc[0][nt], af[0], b0, b1);
                mma_tf32(acc[1][nt], af[1], b0, b1);
            }
        }
        __syncthreads();
        if (kt + 2 < 32)
            pa_load(sm, s, kt + 2, enc, Wc, m0, n0, tid);
    }

    /* epilogue: rank-1 + bias, tanh, multiply by state, reduce over h */
    const int bidx = m0 >> 10;
    const float* st = g_state + bidx * HH;
    #pragma unroll
    for (int mt = 0; mt < 2; mt++) {
        int rg = m0 + wm * 32 + mt * 16 + gid;
        float b0v = bin[rg], b1v = bin[rg + 8];
        float p0 = 0.f, p1 = 0.f;
        #pragma unroll
        for (int nt = 0; nt < 8; nt++) {
            int c0 = n0 + wn * 64 + nt * 8 + tig * 2;
            float ws0 = g_wsum[c0], ws1 = g_wsum[c0 + 1];
            float bb0 = Wcb[c0],    bb1 = Wcb[c0 + 1];
            float s0  = st[c0],     s1  = st[c0 + 1];
            p0 += tanh_fast(acc[mt][nt][0] + b0v * ws0 + bb0) * s0
                + tanh_fast(acc[mt][nt][1] + b0v * ws1 + bb1) * s1;
            p1 += tanh_fast(acc[mt][nt][2] + b1v * ws0 + bb0) * s0
                + tanh_fast(acc[mt][nt][3] + b1v * ws1 + bb1) * s1;
        }
        p0 += __shfl_xor_sync(0xffffffffu, p0, 1);
        p0 += __shfl_xor_sync(0xffffffffu, p0, 2);
        p1 += __shfl_xor_sync(0xffffffffu, p1, 1);
        p1 += __shfl_xor_sync(0xffffffffu, p1, 2);
        if (tig == 0) {
            atomicAdd(&g_score_c[rg], p0);
            atomicAdd(&g_score_c[rg + 8], p1);
        }
    }
}

/* ------------- finalize score_c: tanh + mask --------------------------- */
__global__ void k_fin(const int* __restrict__ eidx) {
    int m = blockIdx.x * blockDim.x + threadIdx.x;
    if (m >= MM) return;
    float v = tanhf(g_score_c[m]);
    if (eidx[m] == 0) v -= 1000.f;
    g_score_c[m] = v;
}

/* ------------- per-row softmax stats (1024 threads) --------------------- */
__global__ void __launch_bounds__(1024) k_rowstats() {
    __shared__ float red[1024];
    const int b = blockIdx.x, tid = threadIdx.x;
    const float* sg = g_score_g + b * VV;
    const float* sc = g_score_c + b * SS;
    float mx = -1e30f;
    for (int i = tid; i < VV; i += 1024) mx = fmaxf(mx, sg[i]);
    for (int i = tid; i < SS; i += 1024) mx = fmaxf(mx, sc[i]);
    red[tid] = mx; __syncthreads();
    for (int o = 512; o; o >>= 1) { if (tid < o) red[tid] = fmaxf(red[tid], red[tid + o]); __syncthreads(); }
    mx = red[0]; __syncthreads();

    float zg = 0.f;
    for (int i = tid; i < VV; i += 1024) zg += expf(sg[i] - mx);
    float zc = 0.f;
    for (int i = tid; i < SS; i += 1024) zc += expf(sc[i] - mx);
    red[tid] = zg + zc; __syncthreads();
    for (int o = 512; o; o >>= 1) { if (tid < o) red[tid] += red[tid + o]; __syncthreads(); }
    float Z = red[0]; __syncthreads();
    red[tid] = zc; __syncthreads();
    for (int o = 512; o; o >>= 1) { if (tid < o) red[tid] += red[tid + o]; __syncthreads(); }
    if (tid == 0) { g_max[b] = mx; g_Z[b] = Z; g_Sc[b] = red[0]; }
}

__global__ void k_compC() {
    int t = threadIdx.x;
    float v = (t < BB) ? g_Sc[t] / g_Z[t] : 0.f;
    #pragma unroll
    for (int o = 16; o; o >>= 1) v += __shfl_xor_sync(0xffffffffu, v, o);
    if (t == 0) g_C[0] = v;
}

/* ------------- output: base probs -------------------------------------- */
__global__ void k_outbase(float* __restrict__ o_out) {
    int i = blockIdx.x * blockDim.x + threadIdx.x;
    if (i >= BB * VO) return;
    int b = i / VO, v = i - b * VO;
    o_out[i] = (v < VV) ? expf(g_score_g[b * VV + v] - g_max[b]) / g_Z[b] : 1e-4f;
}

/* ------------- output: scatter-add prob_c ------------------------------- */
__global__ void k_scatter(const int* __restrict__ eidx, float* __restrict__ o_out) {
    int m = blockIdx.x * blockDim.x + threadIdx.x;
    if (m >= MM) return;
    int b = m >> 10;
    float p = expf(g_score_c[m] - g_max[b]) / g_Z[b];
    atomicAdd(o_out + b * VO + eidx[m], p);
}

/* ------------- weighted_out (sparse attn over idx matches) -------------- */
__global__ void k_weighted(const int* __restrict__ input_idx,
                           const int* __restrict__ eidx,
                           const float* __restrict__ encoded,
                           const float* __restrict__ bin,
                           float* __restrict__ o_w) {
    __shared__ int cnt;
    __shared__ int sl[SS];
    __shared__ float av[SS];
    const int b = blockIdx.x, tid = threadIdx.x;
    if (tid == 0) cnt = 0;
    __syncthreads();
    int target = input_idx[b];
    for (int s = tid; s < SS; s += 256)
        if (eidx[b * SS + s] == target) { int p = atomicAdd(&cnt, 1); sl[p] = s; }
    __syncthreads();
    int n = cnt;
    float scale = (n > 1) ? 1.f / (float)n : 1.f;
    for (int i = tid; i < n; i += 256) {
        int s = sl[i];
        float pc = expf(g_score_c[b * SS + s] - g_max[b]) / g_Z[b];
        av[i] = pc / g_C[0] * scale;
    }
    __syncthreads();
    for (int d = tid; d < DD2; d += 256) {
        float acc = 0.f;
        for (int i = 0; i < n; i++) {
            int s = sl[i];
            float e = (d < 2 * HH) ? encoded[(size_t)(b * SS + s) * (2 * HH) + d]
                                   : bin[b * SS + s];
            acc += av[i] * e;
        }
        o_w[b * DD2 + d] = acc;
    }
}

/* ======================= host launcher ================================== */
extern "C" void kernel_launch(void* const* d_in, const int* in_sizes, int n_in,
                              void* d_out, int out_size) {
    const int*   input_idx = (const int*)  d_in[0];
    const float* encoded   = (const float*)d_in[1];
    const int*   eidx      = (const int*)  d_in[2];
    const float* prev      = (const float*)d_in[3];
    const float* weighted  = (const float*)d_in[4];
    const float* bin       = (const float*)d_in[5];
    /* d_in[6] = order (always 1) */
    const float* embed     = (const float*)d_in[7];
    const float* W_ih      = (const float*)d_in[8];
    const float* b_ih      = (const float*)d_in[9];
    const float* W_hh      = (const float*)d_in[10];
    const float* b_hh      = (const float*)d_in[11];
    const float* Wo_w      = (const float*)d_in[12];
    const float* Wo_b      = (const float*)d_in[13];
    const float* Wc_w      = (const float*)d_in[14];
    const float* Wc_b      = (const float*)d_in[15];

    float* o_out   = (float*)d_out;
    float* o_state = o_out + (size_t)BB * VO;
    float* o_w     = o_state + (size_t)BB * HH;

    cudaFuncSetAttribute(k_passA, cudaFuncAttributeMaxDynamicSharedMemorySize,
                         PA_SMEM);

    int prep_n = BB * ININ + HH + MM;
    k_prep<<<(prep_n + 255) / 256, 256>>>(input_idx, embed, weighted, Wc_w);
    k_gru<<<48, 256>>>(W_ih, b_ih, W_hh, b_hh, prev);
    k_gates<<<(BB * HH + 255) / 256, 256>>>(prev, o_state);
    k_sg<<<VV / 128, 256>>>(Wo_w, Wo_b);
    {
        dim3 grid(HH / 128, MM / 128);   /* n fastest -> 4 CTAs share each A tile */
        k_passA<<<grid, 256, PA_SMEM>>>(encoded, Wc_w, Wc_b, bin);
    }
    k_fin<<<MM / 256, 256>>>(eidx);
    k_rowstats<<<BB, 1024>>>();
    k_compC<<<1, 32>>>();
    k_outbase<<<(BB * VO + 255) / 256, 256>>>(o_out);
    k_scatter<<<MM / 256, 256>>>(eidx, o_out);
    k_weighted<<<BB, 256>>>(input_idx, eidx, encoded, bin, o_w);
}

// round 14
// speedup vs baseline: 1.7706x; 1.1906x over previous
#include <cuda_runtime.h>
#include <cuda_fp16.h>
#include <math.h>
#include <stdint.h>

#define BB    32
#define SS    1024
#define VV    32000
#define EE    256
#define HH    512
#define OOV   12
#define DD2   1124
#define ININ  1380
#define MM    (BB*SS)
#define VO    (VV+OOV)
#define H3    (3*HH)

/* ------------- device scratch (no allocation allowed) ------------------ */
__device__ float g_x[BB*ININ];
__device__ float g_wsum[HH];
__device__ float g_gi[BB*H3];
__device__ float g_gh[BB*H3];
__device__ float g_state[BB*HH];
__device__ float g_score_g[BB*VV];
__device__ float g_score_c[MM];
__device__ float g_max[BB], g_Z[BB], g_Sc[BB], g_C[1];
__device__ __half g_ench[(size_t)MM*1024];   /* enc[:, :1024] in fp16 */
__device__ __half g_wch[HH*1024];            /* Wc[:, :1024] in fp16  */

/* ------------- helpers ------------------------------------------------- */
__device__ __forceinline__ float tanh_fast(float x) {
    float y;
    asm("tanh.approx.f32 %0, %1;" : "=f"(y) : "f"(x));
    return y;
}
__device__ __forceinline__ uint32_t smem_u32(const void* p) {
    uint32_t a;
    asm("{ .reg .u64 t; cvta.to.shared.u64 t, %1; cvt.u32.u64 %0, t; }"
        : "=r"(a) : "l"(p));
    return a;
}
__device__ __forceinline__ void mma_tf32(float* d, const unsigned* a,
                                         unsigned b0, unsigned b1) {
    asm volatile(
        "mma.sync.aligned.m16n8k8.row.col.f32.tf32.tf32.f32 "
        "{%0,%1,%2,%3}, {%4,%5,%6,%7}, {%8,%9}, {%0,%1,%2,%3};\n"
        : "+f"(d[0]), "+f"(d[1]), "+f"(d[2]), "+f"(d[3])
        : "r"(a[0]), "r"(a[1]), "r"(a[2]), "r"(a[3]), "r"(b0), "r"(b1));
}
__device__ __forceinline__ void mma_f16(float* d, const unsigned* a,
                                        unsigned b0, unsigned b1) {
    asm volatile(
        "mma.sync.aligned.m16n8k16.row.col.f32.f16.f16.f32 "
        "{%0,%1,%2,%3}, {%4,%5,%6,%7}, {%8,%9}, {%0,%1,%2,%3};\n"
        : "+f"(d[0]), "+f"(d[1]), "+f"(d[2]), "+f"(d[3])
        : "r"(a[0]), "r"(a[1]), "r"(a[2]), "r"(a[3]), "r"(b0), "r"(b1));
}

#define CPA16(dst, src) \
    asm volatile("cp.async.cg.shared.global [%0], [%1], 16;" \
                 :: "r"(dst), "l"(src) : "memory")
#define CPA_COMMIT()  asm volatile("cp.async.commit_group;" ::: "memory")
#define CPA_WAIT1()   asm volatile("cp.async.wait_group 1;" ::: "memory")
#define CPA_WAIT0()   asm volatile("cp.async.wait_group 0;" ::: "memory")

/* passA smem (fp16): 2 stages x (A 128x36 + B 128x36) uint32          */
/* each row: 32 data u32 (= 64 halves) + 4 pad                          */
#define PA_ROW     36
#define PA_ATILE   (128*PA_ROW)          /* uint32 */
#define PA_STAGE   (2*PA_ATILE)
#define PA_SMEM_U  (2*PA_STAGE)
#define PA_SMEM    (PA_SMEM_U*4)         /* 73728 bytes */

/* k_sg smem: 2 stages x (A 32x36 + B 128x36) floats = 46080 B */
#define SG_ROW     36
#define SG_ATILE   (32*SG_ROW)
#define SG_BTILE   (128*SG_ROW)
#define SG_STAGE   (SG_ATILE + SG_BTILE)

/* ------------- fp16 conversion: enc[:, :1024] and Wc[:, :1024] --------- */
#define CV_ENC4 ((size_t)MM*1024/4)      /* 8388608 float4s */
#define CV_WC4  (HH*1024/4)              /* 131072 float4s  */
__global__ void k_conv(const float* __restrict__ enc,
                       const float* __restrict__ Wc) {
    size_t i = (size_t)blockIdx.x * blockDim.x + threadIdx.x;
    if (i < CV_ENC4) {
        float4 v = ((const float4*)enc)[i];
        __half2* dst = (__half2*)g_ench + i * 2;
        dst[0] = __floats2half2_rn(v.x, v.y);
        dst[1] = __floats2half2_rn(v.z, v.w);
    } else if (i < CV_ENC4 + CV_WC4) {
        size_t j = i - CV_ENC4;
        int row = (int)(j >> 8), c4 = (int)(j & 255);
        float4 v = *(const float4*)(Wc + (size_t)row * DD2 + c4 * 4);
        __half2* dst = (__half2*)(g_wch + row * 1024 + c4 * 4);
        dst[0] = __floats2half2_rn(v.x, v.y);
        dst[1] = __floats2half2_rn(v.z, v.w);
    }
}

/* ------------- prep: x=[emb|weighted], wsum, zero score_c -------------- */
__global__ void k_prep(const int* __restrict__ input_idx,
                       const float* __restrict__ embed,
                       const float* __restrict__ weighted,
                       const float* __restrict__ Wc) {
    int i = blockIdx.x * blockDim.x + threadIdx.x;
    if (i < BB * ININ) {
        int b = i / ININ, j = i - b * ININ;
        g_x[i] = (j < EE) ? embed[input_idx[b] * EE + j]
                          : weighted[b * DD2 + (j - EE)];
    } else if (i < BB * ININ + HH) {
        int h = i - BB * ININ;
        float s = 0.f;
        #pragma unroll 4
        for (int j = 0; j < 100; j++) s += Wc[h * DD2 + 2 * HH + j];
        g_wsum[h] = s;
    } else if (i < BB * ININ + HH + MM) {
        g_score_c[i - BB * ININ - HH] = 0.f;
    }
}

/* ------------- generic small-N SIMT GEMM core -------------------------- */
template<int RP>
__device__ __forceinline__ void gemm_core(float (*Ws)[33], float (*Xs)[33], int r0,
                                          const float* __restrict__ W, int ldw,
                                          const float* __restrict__ X, int ldx,
                                          const float* __restrict__ bias,
                                          float* __restrict__ out, int ldo, int K) {
    const int tid = threadIdx.x;
    const int vi  = tid & 31, bi = tid >> 5;
    float acc[RP][4];
    #pragma unroll
    for (int p = 0; p < RP; p++)
        #pragma unroll
        for (int q = 0; q < 4; q++) acc[p][q] = 0.f;

    for (int kc = 0; kc < K; kc += 32) {
        for (int e = tid; e < RP * 32 * 32; e += 256) {
            int row = e >> 5, k = e & 31;
            Ws[row][k] = (kc + k < K) ? W[(r0 + row) * ldw + kc + k] : 0.f;
        }
        for (int e = tid; e < 32 * 32; e += 256) {
            int row = e >> 5, k = e & 31;
            Xs[row][k] = (kc + k < K) ? X[row * ldx + kc + k] : 0.f;
        }
        __syncthreads();
        #pragma unroll
        for (int k = 0; k < 32; k++) {
            float x[4];
            #pragma unroll
            for (int q = 0; q < 4; q++) x[q] = Xs[bi * 4 + q][k];
            #pragma unroll
            for (int p = 0; p < RP; p++) {
                float w = Ws[vi + 32 * p][k];
                #pragma unroll
                for (int q = 0; q < 4; q++) acc[p][q] += w * x[q];
            }
        }
        __syncthreads();
    }
    #pragma unroll
    for (int p = 0; p < RP; p++) {
        int r = r0 + vi + 32 * p;
        float bv = bias[r];
        #pragma unroll
        for (int q = 0; q < 4; q++)
            out[(bi * 4 + q) * ldo + r] = acc[p][q] + bv;
    }
}

/* merged GRU input/hidden GEMMs */
__global__ void __launch_bounds__(256) k_gru(const float* __restrict__ W_ih,
                                             const float* __restrict__ b_ih,
                                             const float* __restrict__ W_hh,
                                             const float* __restrict__ b_hh,
                                             const float* __restrict__ prev) {
    __shared__ float Ws[64][33]; __shared__ float Xs[32][33];
    if (blockIdx.x < 24)
        gemm_core<2>(Ws, Xs, blockIdx.x * 64, W_ih, ININ, g_x, ININ, b_ih, g_gi, H3, ININ);
    else
        gemm_core<2>(Ws, Xs, (blockIdx.x - 24) * 64, W_hh, HH, prev, HH, b_hh, g_gh, H3, HH);
}

/* ------------- score_g: tf32 mma streaming GEMM ------------------------ */
__device__ __forceinline__ void sg_load(float* sm, int stage, int chunk,
                                        const float* __restrict__ W,
                                        int n0, int tid) {
    float* As = sm + stage * SG_STAGE;
    float* Bs = As + SG_ATILE;
    const uint32_t a_u = smem_u32(As);
    const uint32_t b_u = smem_u32(Bs);
    const int kc = chunk * 32;
    {
        int row = tid >> 3, q = tid & 7;
        CPA16(a_u + (uint32_t)(row * SG_ROW + q * 4) * 4,
              g_state + row * HH + kc + q * 4);
    }
    #pragma unroll
    for (int j = 0; j < 4; j++) {
        int u = tid + j * 256;
        int row = u >> 3, q = u & 7;
        CPA16(b_u + (uint32_t)(row * SG_ROW + q * 4) * 4,
              W + (size_t)(n0 + row) * HH + kc + q * 4);
    }
    CPA_COMMIT();
}

__global__ void __launch_bounds__(256, 2) k_sg(const float* __restrict__ W,
                                               const float* __restrict__ bias) {
    __shared__ __align__(16) float sm[2 * SG_STAGE];
    const int tid  = threadIdx.x;
    const int lane = tid & 31, warp = tid >> 5;
    const int gid  = lane >> 2, tig = lane & 3;
    const int n0   = blockIdx.x * 128;

    float acc[2][2][4];
    #pragma unroll
    for (int a = 0; a < 2; a++)
        #pragma unroll
        for (int b = 0; b < 2; b++)
            #pragma unroll
            for (int c = 0; c < 4; c++) acc[a][b][c] = 0.f;

    sg_load(sm, 0, 0, W, n0, tid);
    sg_load(sm, 1, 1, W, n0, tid);

    for (int kt = 0; kt < 16; kt++) {
        const int s = kt & 1;
        if (kt < 15) { CPA_WAIT1(); } else { CPA_WAIT0(); }
        __syncthreads();

        const float* As = sm + s * SG_STAGE;
        const float* Bs = As + SG_ATILE;
        #pragma unroll
        for (int ks = 0; ks < 4; ks++) {
            const int kb = ks * 8;
            unsigned af[2][4];
            #pragma unroll
            for (int mt = 0; mt < 2; mt++) {
                int r = mt * 16 + gid;
                af[mt][0] = __float_as_uint(As[r * SG_ROW + kb + tig]);
                af[mt][1] = __float_as_uint(As[(r + 8) * SG_ROW + kb + tig]);
                af[mt][2] = __float_as_uint(As[r * SG_ROW + kb + tig + 4]);
                af[mt][3] = __float_as_uint(As[(r + 8) * SG_ROW + kb + tig + 4]);
            }
            #pragma unroll
            for (int nt = 0; nt < 2; nt++) {
                int c = warp * 16 + nt * 8 + gid;
                unsigned b0 = __float_as_uint(Bs[c * SG_ROW + kb + tig]);
                unsigned b1 = __float_as_uint(Bs[c * SG_ROW + kb + tig + 4]);
                mma_tf32(acc[0][nt], af[0], b0, b1);
                mma_tf32(acc[1][nt], af[1], b0, b1);
            }
        }
        __syncthreads();
        if (kt + 2 < 16)
            sg_load(sm, s, kt + 2, W, n0, tid);
    }

    #pragma unroll
    for (int mt = 0; mt < 2; mt++) {
        #pragma unroll
        for (int nt = 0; nt < 2; nt++) {
            int br = mt * 16 + gid;
            int c  = n0 + warp * 16 + nt * 8 + tig * 2;
            float bi0 = bias[c], bi1 = bias[c + 1];
            g_score_g[br * VV + c]           = acc[mt][nt][0] + bi0;
            g_score_g[br * VV + c + 1]       = acc[mt][nt][1] + bi1;
            g_score_g[(br + 8) * VV + c]     = acc[mt][nt][2] + bi0;
            g_score_g[(br + 8) * VV + c + 1] = acc[mt][nt][3] + bi1;
        }
    }
}

/* ------------- GRU gate combine ---------------------------------------- */
__global__ void k_gates(const float* __restrict__ prev, float* __restrict__ o_state) {
    int idx = blockIdx.x * blockDim.x + threadIdx.x;
    if (idx >= BB * HH) return;
    int b = idx >> 9, h = idx & (HH - 1);
    const float* gi = g_gi + b * H3;
    const float* gh = g_gh + b * H3;
    float r  = 1.f / (1.f + expf(-(gi[h] + gh[h])));
    float z  = 1.f / (1.f + expf(-(gi[HH + h] + gh[HH + h])));
    float nn = tanhf(gi[2 * HH + h] + r * gh[2 * HH + h]);
    float st = (1.f - z) * nn + z * prev[idx];
    g_state[idx] = st;
    o_state[idx] = st;
}

/* ------------- pass A: fp16 m16n8k16 mma, cp.async double-buffered ------ */
/* k-chunk = 64 halves (128 B/row), 16 chunks over K=1024                  */
__device__ __forceinline__ void pa_load(uint32_t* sm, int stage, int chunk,
                                        int m0, int n0, int tid) {
    uint32_t* As = sm + stage * PA_STAGE;
    uint32_t* Bs = As + PA_ATILE;
    const uint32_t a_u32 = smem_u32(As);
    const uint32_t b_u32 = smem_u32(Bs);
    const int kc = chunk * 64;           /* halves */
    #pragma unroll
    for (int j = 0; j < 4; j++) {
        int u = tid + j * 256;           /* 0..1023: 128 rows x 8 (16B) */
        int row = u >> 3, q = u & 7;
        CPA16(a_u32 + (uint32_t)(row * PA_ROW + q * 4) * 4,
              g_ench + (size_t)(m0 + row) * 1024 + kc + q * 8);
        CPA16(b_u32 + (uint32_t)(row * PA_ROW + q * 4) * 4,
              g_wch + (size_t)(n0 + row) * 1024 + kc + q * 8);
    }
    CPA_COMMIT();
}

__global__ void __launch_bounds__(256, 2) k_passA(const float* __restrict__ Wcb,
                                                  const float* __restrict__ bin) {
    extern __shared__ __align__(16) uint32_t smu[];
    const int tid  = threadIdx.x;
    const int lane = tid & 31, warp = tid >> 5;
    const int gid  = lane >> 2, tig = lane & 3;
    const int wm   = warp & 3, wn = warp >> 2;        /* 4 x 2 warps */
    const int m0   = blockIdx.y * 128;
    const int n0   = blockIdx.x * 128;

    float acc[2][8][4];
    #pragma unroll
    for (int a = 0; a < 2; a++)
        #pragma unroll
        for (int b = 0; b < 8; b++)
            #pragma unroll
            for (int c = 0; c < 4; c++) acc[a][b][c] = 0.f;

    pa_load(smu, 0, 0, m0, n0, tid);
    pa_load(smu, 1, 1, m0, n0, tid);

    for (int kt = 0; kt < 16; kt++) {
        const int s = kt & 1;
        if (kt < 15) { CPA_WAIT1(); } else { CPA_WAIT0(); }
        __syncthreads();

        const uint32_t* As = smu + s * PA_STAGE;
        const uint32_t* Bs = As + PA_ATILE;
        #pragma unroll
        for (int ks = 0; ks < 4; ks++) {       /* 4 x k16 per 64-half chunk */
            const int kb = ks * 8;             /* uint32 offset in row */
            unsigned af[2][4];
            #pragma unroll
            for (int mt = 0; mt < 2; mt++) {
                int r = wm * 32 + mt * 16 + gid;
                af[mt][0] = As[r * PA_ROW + kb + tig];
                af[mt][1] = As[(r + 8) * PA_ROW + kb + tig];
                af[mt][2] = As[r * PA_ROW + kb + 4 + tig];
                af[mt][3] = As[(r + 8) * PA_ROW + kb + 4 + tig];
            }
            #pragma unroll
            for (int nt = 0; nt < 8; nt++) {
                int c = wn * 64 + nt * 8 + gid;
                unsigned b0 = Bs[c * PA_ROW + kb + tig];
                unsigned b1 = Bs[c * PA_ROW + kb + 4 + tig];
                mma_f16(acc[0][nt], af[0], b0, b1);
                mma_f16(acc[1][nt], af[1], b0, b1);
            }
        }
        __syncthreads();
        if (kt + 2 < 16)
            pa_load(smu, s, kt + 2, m0, n0, tid);
    }

    /* epilogue: rank-1 + bias, tanh, multiply by state, reduce over h */
    const int bidx = m0 >> 10;
    const float* st = g_state + bidx * HH;
    #pragma unroll
    for (int mt = 0; mt < 2; mt++) {
        int rg = m0 + wm * 32 + mt * 16 + gid;
        float b0v = bin[rg], b1v = bin[rg + 8];
        float p0 = 0.f, p1 = 0.f;
        #pragma unroll
        for (int nt = 0; nt < 8; nt++) {
            int c0 = n0 + wn * 64 + nt * 8 + tig * 2;
            float ws0 = g_wsum[c0], ws1 = g_wsum[c0 + 1];
            float bb0 = Wcb[c0],    bb1 = Wcb[c0 + 1];
            float s0  = st[c0],     s1  = st[c0 + 1];
            p0 += tanh_fast(acc[mt][nt][0] + b0v * ws0 + bb0) * s0
                + tanh_fast(acc[mt][nt][1] + b0v * ws1 + bb1) * s1;
            p1 += tanh_fast(acc[mt][nt][2] + b1v * ws0 + bb0) * s0
                + tanh_fast(acc[mt][nt][3] + b1v * ws1 + bb1) * s1;
        }
        p0 += __shfl_xor_sync(0xffffffffu, p0, 1);
        p0 += __shfl_xor_sync(0xffffffffu, p0, 2);
        p1 += __shfl_xor_sync(0xffffffffu, p1, 1);
        p1 += __shfl_xor_sync(0xffffffffu, p1, 2);
        if (tig == 0) {
            atomicAdd(&g_score_c[rg], p0);
            atomicAdd(&g_score_c[rg + 8], p1);
        }
    }
}

/* ------------- finalize score_c: tanh + mask --------------------------- */
__global__ void k_fin(const int* __restrict__ eidx) {
    int m = blockIdx.x * blockDim.x + threadIdx.x;
    if (m >= MM) return;
    float v = tanhf(g_score_c[m]);
    if (eidx[m] == 0) v -= 1000.f;
    g_score_c[m] = v;
}

/* ------------- per-row softmax stats (1024 threads) --------------------- */
__global__ void __launch_bounds__(1024) k_rowstats() {
    __shared__ float red[1024];
    const int b = blockIdx.x, tid = threadIdx.x;
    const float* sg = g_score_g + b * VV;
    const float* sc = g_score_c + b * SS;
    float mx = -1e30f;
    for (int i = tid; i < VV; i += 1024) mx = fmaxf(mx, sg[i]);
    for (int i = tid; i < SS; i += 1024) mx = fmaxf(mx, sc[i]);
    red[tid] = mx; __syncthreads();
    for (int o = 512; o; o >>= 1) { if (tid < o) red[tid] = fmaxf(red[tid], red[tid + o]); __syncthreads(); }
    mx = red[0]; __syncthreads();

    float zg = 0.f;
    for (int i = tid; i < VV; i += 1024) zg += expf(sg[i] - mx);
    float zc = 0.f;
    for (int i = tid; i < SS; i += 1024) zc += expf(sc[i] - mx);
    red[tid] = zg + zc; __syncthreads();
    for (int o = 512; o; o >>= 1) { if (tid < o) red[tid] += red[tid + o]; __syncthreads(); }
    float Z = red[0]; __syncthreads();
    red[tid] = zc; __syncthreads();
    for (int o = 512; o; o >>= 1) { if (tid < o) red[tid] += red[tid + o]; __syncthreads(); }
    if (tid == 0) { g_max[b] = mx; g_Z[b] = Z; g_Sc[b] = red[0]; }
}

__global__ void k_compC() {
    int t = threadIdx.x;
    float v = (t < BB) ? g_Sc[t] / g_Z[t] : 0.f;
    #pragma unroll
    for (int o = 16; o; o >>= 1) v += __shfl_xor_sync(0xffffffffu, v, o);
    if (t == 0) g_C[0] = v;
}

/* ------------- output: base probs -------------------------------------- */
__global__ void k_outbase(float* __restrict__ o_out) {
    int i = blockIdx.x * blockDim.x + threadIdx.x;
    if (i >= BB * VO) return;
    int b = i / VO, v = i - b * VO;
    o_out[i] = (v < VV) ? expf(g_score_g[b * VV + v] - g_max[b]) / g_Z[b] : 1e-4f;
}

/* ------------- output: scatter-add prob_c ------------------------------- */
__global__ void k_scatter(const int* __restrict__ eidx, float* __restrict__ o_out) {
    int m = blockIdx.x * blockDim.x + threadIdx.x;
    if (m >= MM) return;
    int b = m >> 10;
    float p = expf(g_score_c[m] - g_max[b]) / g_Z[b];
    atomicAdd(o_out + b * VO + eidx[m], p);
}

/* ------------- weighted_out (sparse attn over idx matches) -------------- */
__global__ void k_weighted(const int* __restrict__ input_idx,
                           const int* __restrict__ eidx,
                           const float* __restrict__ encoded,
                           const float* __restrict__ bin,
                           float* __restrict__ o_w) {
    __shared__ int cnt;
    __shared__ int sl[SS];
    __shared__ float av[SS];
    const int b = blockIdx.x, tid = threadIdx.x;
    if (tid == 0) cnt = 0;
    __syncthreads();
    int target = input_idx[b];
    for (int s = tid; s < SS; s += 256)
        if (eidx[b * SS + s] == target) { int p = atomicAdd(&cnt, 1); sl[p] = s; }
    __syncthreads();
    int n = cnt;
    float scale = (n > 1) ? 1.f / (float)n : 1.f;
    for (int i = tid; i < n; i += 256) {
        int s = sl[i];
        float pc = expf(g_score_c[b * SS + s] - g_max[b]) / g_Z[b];
        av[i] = pc / g_C[0] * scale;
    }
    __syncthreads();
    for (int d = tid; d < DD2; d += 256) {
        float acc = 0.f;
        for (int i = 0; i < n; i++) {
            int s = sl[i];
            float e = (d < 2 * HH) ? encoded[(size_t)(b * SS + s) * (2 * HH) + d]
                                   : bin[b * SS + s];
            acc += av[i] * e;
        }
        o_w[b * DD2 + d] = acc;
    }
}

/* ======================= host launcher ================================== */
extern "C" void kernel_launch(void* const* d_in, const int* in_sizes, int n_in,
                              void* d_out, int out_size) {
    const int*   input_idx = (const int*)  d_in[0];
    const float* encoded   = (const float*)d_in[1];
    const int*   eidx      = (const int*)  d_in[2];
    const float* prev      = (const float*)d_in[3];
    const float* weighted  = (const float*)d_in[4];
    const float* bin       = (const float*)d_in[5];
    /* d_in[6] = order (always 1) */
    const float* embed     = (const float*)d_in[7];
    const float* W_ih      = (const float*)d_in[8];
    const float* b_ih      = (const float*)d_in[9];
    const float* W_hh      = (const float*)d_in[10];
    const float* b_hh      = (const float*)d_in[11];
    const float* Wo_w      = (const float*)d_in[12];
    const float* Wo_b      = (const float*)d_in[13];
    const float* Wc_w      = (const float*)d_in[14];
    const float* Wc_b      = (const float*)d_in[15];

    float* o_out   = (float*)d_out;
    float* o_state = o_out + (size_t)BB * VO;
    float* o_w     = o_state + (size_t)BB * HH;

    cudaFuncSetAttribute(k_passA, cudaFuncAttributeMaxDynamicSharedMemorySize,
                         PA_SMEM);

    {
        size_t tot = CV_ENC4 + CV_WC4;
        k_conv<<<(unsigned)((tot + 255) / 256), 256>>>(encoded, Wc_w);
    }
    int prep_n = BB * ININ + HH + MM;
    k_prep<<<(prep_n + 255) / 256, 256>>>(input_idx, embed, weighted, Wc_w);
    k_gru<<<48, 256>>>(W_ih, b_ih, W_hh, b_hh, prev);
    k_gates<<<(BB * HH + 255) / 256, 256>>>(prev, o_state);
    k_sg<<<VV / 128, 256>>>(Wo_w, Wo_b);
    {
        dim3 grid(HH / 128, MM / 128);   /* n fastest */
        k_passA<<<grid, 256, PA_SMEM>>>(Wc_b, bin);
    }
    k_fin<<<MM / 256, 256>>>(eidx);
    k_rowstats<<<BB, 1024>>>();
    k_compC<<<1, 32>>>();
    k_outbase<<<(BB * VO + 255) / 256, 256>>>(o_out);
    k_scatter<<<MM / 256, 256>>>(eidx, o_out);
    k_weighted<<<BB, 256>>>(input_idx, eidx, encoded, bin, o_w);
}

// round 15
// speedup vs baseline: 1.8638x; 1.0526x over previous
#include <cuda_runtime.h>
#include <cuda_fp16.h>
#include <math.h>
#include <stdint.h>

#define BB    32
#define SS    1024
#define VV    32000
#define EE    256
#define HH    512
#define OOV   12
#define DD2   1124
#define ININ  1380
#define MM    (BB*SS)
#define VO    (VV+OOV)
#define H3    (3*HH)

/* ------------- device scratch (no allocation allowed) ------------------ */
__device__ float g_x[BB*ININ];
__device__ float g_wsum[HH];
__device__ float g_gi[BB*H3];
__device__ float g_gh[BB*H3];
__device__ float g_state[BB*HH];
__device__ float g_score_g[BB*VV];
__device__ float g_score_c[MM];
__device__ float g_max[BB], g_Z[BB], g_Sc[BB], g_C[1];
__device__ __half g_ench[(size_t)MM*1024];   /* enc[:, :1024] in fp16 */
__device__ __half g_wch[HH*1024];            /* Wc[:, :1024] in fp16  */

/* ------------- helpers ------------------------------------------------- */
__device__ __forceinline__ float tanh_fast(float x) {
    float y;
    asm("tanh.approx.f32 %0, %1;" : "=f"(y) : "f"(x));
    return y;
}
__device__ __forceinline__ uint32_t smem_u32(const void* p) {
    uint32_t a;
    asm("{ .reg .u64 t; cvta.to.shared.u64 t, %1; cvt.u32.u64 %0, t; }"
        : "=r"(a) : "l"(p));
    return a;
}
__device__ __forceinline__ void mma_tf32(float* d, const unsigned* a,
                                         unsigned b0, unsigned b1) {
    asm volatile(
        "mma.sync.aligned.m16n8k8.row.col.f32.tf32.tf32.f32 "
        "{%0,%1,%2,%3}, {%4,%5,%6,%7}, {%8,%9}, {%0,%1,%2,%3};\n"
        : "+f"(d[0]), "+f"(d[1]), "+f"(d[2]), "+f"(d[3])
        : "r"(a[0]), "r"(a[1]), "r"(a[2]), "r"(a[3]), "r"(b0), "r"(b1));
}
__device__ __forceinline__ void mma_f16(float* d, const unsigned* a,
                                        unsigned b0, unsigned b1) {
    asm volatile(
        "mma.sync.aligned.m16n8k16.row.col.f32.f16.f16.f32 "
        "{%0,%1,%2,%3}, {%4,%5,%6,%7}, {%8,%9}, {%0,%1,%2,%3};\n"
        : "+f"(d[0]), "+f"(d[1]), "+f"(d[2]), "+f"(d[3])
        : "r"(a[0]), "r"(a[1]), "r"(a[2]), "r"(a[3]), "r"(b0), "r"(b1));
}
#define LDM_X4(r0, r1, r2, r3, addr) \
    asm volatile("ldmatrix.sync.aligned.m8n8.x4.shared.b16 {%0,%1,%2,%3}, [%4];" \
                 : "=r"(r0), "=r"(r1), "=r"(r2), "=r"(r3) : "r"(addr))

#define CPA16(dst, src) \
    asm volatile("cp.async.cg.shared.global [%0], [%1], 16;" \
                 :: "r"(dst), "l"(src) : "memory")
#define CPA_COMMIT()  asm volatile("cp.async.commit_group;" ::: "memory")
#define CPA_WAIT1()   asm volatile("cp.async.wait_group 1;" ::: "memory")
#define CPA_WAIT0()   asm volatile("cp.async.wait_group 0;" ::: "memory")

/* passA smem (fp16): 2 stages x (A 128x36 + B 128x36) uint32 */
#define PA_ROW     36
#define PA_ATILE   (128*PA_ROW)          /* uint32 */
#define PA_STAGE   (2*PA_ATILE)
#define PA_SMEM_U  (2*PA_STAGE)
#define PA_SMEM    (PA_SMEM_U*4)         /* 73728 bytes */

/* k_sg smem: 2 stages x (A 32x36 + B 128x36) floats = 46080 B */
#define SG_ROW     36
#define SG_ATILE   (32*SG_ROW)
#define SG_BTILE   (128*SG_ROW)
#define SG_STAGE   (SG_ATILE + SG_BTILE)

/* ------------- fp16 conversion: enc[:, :1024] and Wc[:, :1024] --------- */
#define CV_ENC4 ((size_t)MM*1024/4)
#define CV_WC4  (HH*1024/4)
__global__ void k_conv(const float* __restrict__ enc,
                       const float* __restrict__ Wc) {
    size_t i = (size_t)blockIdx.x * blockDim.x + threadIdx.x;
    if (i < CV_ENC4) {
        float4 v = ((const float4*)enc)[i];
        __half2* dst = (__half2*)g_ench + i * 2;
        dst[0] = __floats2half2_rn(v.x, v.y);
        dst[1] = __floats2half2_rn(v.z, v.w);
    } else if (i < CV_ENC4 + CV_WC4) {
        size_t j = i - CV_ENC4;
        int row = (int)(j >> 8), c4 = (int)(j & 255);
        float4 v = *(const float4*)(Wc + (size_t)row * DD2 + c4 * 4);
        __half2* dst = (__half2*)(g_wch + row * 1024 + c4 * 4);
        dst[0] = __floats2half2_rn(v.x, v.y);
        dst[1] = __floats2half2_rn(v.z, v.w);
    }
}

/* ------------- prep: x=[emb|weighted], wsum, zero score_c -------------- */
__global__ void k_prep(const int* __restrict__ input_idx,
                       const float* __restrict__ embed,
                       const float* __restrict__ weighted,
                       const float* __restrict__ Wc) {
    int i = blockIdx.x * blockDim.x + threadIdx.x;
    if (i < BB * ININ) {
        int b = i / ININ, j = i - b * ININ;
        g_x[i] = (j < EE) ? embed[input_idx[b] * EE + j]
                          : weighted[b * DD2 + (j - EE)];
    } else if (i < BB * ININ + HH) {
        int h = i - BB * ININ;
        float s = 0.f;
        #pragma unroll 4
        for (int j = 0; j < 100; j++) s += Wc[h * DD2 + 2 * HH + j];
        g_wsum[h] = s;
    } else if (i < BB * ININ + HH + MM) {
        g_score_c[i - BB * ININ - HH] = 0.f;
    }
}

/* ------------- generic small-N SIMT GEMM core -------------------------- */
template<int RP>
__device__ __forceinline__ void gemm_core(float (*Ws)[33], float (*Xs)[33], int r0,
                                          const float* __restrict__ W, int ldw,
                                          const float* __restrict__ X, int ldx,
                                          const float* __restrict__ bias,
                                          float* __restrict__ out, int ldo, int K) {
    const int tid = threadIdx.x;
    const int vi  = tid & 31, bi = tid >> 5;
    float acc[RP][4];
    #pragma unroll
    for (int p = 0; p < RP; p++)
        #pragma unroll
        for (int q = 0; q < 4; q++) acc[p][q] = 0.f;

    for (int kc = 0; kc < K; kc += 32) {
        for (int e = tid; e < RP * 32 * 32; e += 256) {
            int row = e >> 5, k = e & 31;
            Ws[row][k] = (kc + k < K) ? W[(r0 + row) * ldw + kc + k] : 0.f;
        }
        for (int e = tid; e < 32 * 32; e += 256) {
            int row = e >> 5, k = e & 31;
            Xs[row][k] = (kc + k < K) ? X[row * ldx + kc + k] : 0.f;
        }
        __syncthreads();
        #pragma unroll
        for (int k = 0; k < 32; k++) {
            float x[4];
            #pragma unroll
            for (int q = 0; q < 4; q++) x[q] = Xs[bi * 4 + q][k];
            #pragma unroll
            for (int p = 0; p < RP; p++) {
                float w = Ws[vi + 32 * p][k];
                #pragma unroll
                for (int q = 0; q < 4; q++) acc[p][q] += w * x[q];
            }
        }
        __syncthreads();
    }
    #pragma unroll
    for (int p = 0; p < RP; p++) {
        int r = r0 + vi + 32 * p;
        float bv = bias[r];
        #pragma unroll
        for (int q = 0; q < 4; q++)
            out[(bi * 4 + q) * ldo + r] = acc[p][q] + bv;
    }
}

/* merged GRU input/hidden GEMMs */
__global__ void __launch_bounds__(256) k_gru(const float* __restrict__ W_ih,
                                             const float* __restrict__ b_ih,
                                             const float* __restrict__ W_hh,
                                             const float* __restrict__ b_hh,
                                             const float* __restrict__ prev) {
    __shared__ float Ws[64][33]; __shared__ float Xs[32][33];
    if (blockIdx.x < 24)
        gemm_core<2>(Ws, Xs, blockIdx.x * 64, W_ih, ININ, g_x, ININ, b_ih, g_gi, H3, ININ);
    else
        gemm_core<2>(Ws, Xs, (blockIdx.x - 24) * 64, W_hh, HH, prev, HH, b_hh, g_gh, H3, HH);
}

/* ------------- score_g: tf32 mma streaming GEMM ------------------------ */
__device__ __forceinline__ void sg_load(float* sm, int stage, int chunk,
                                        const float* __restrict__ W,
                                        int n0, int tid) {
    float* As = sm + stage * SG_STAGE;
    float* Bs = As + SG_ATILE;
    const uint32_t a_u = smem_u32(As);
    const uint32_t b_u = smem_u32(Bs);
    const int kc = chunk * 32;
    {
        int row = tid >> 3, q = tid & 7;
        CPA16(a_u + (uint32_t)(row * SG_ROW + q * 4) * 4,
              g_state + row * HH + kc + q * 4);
    }
    #pragma unroll
    for (int j = 0; j < 4; j++) {
        int u = tid + j * 256;
        int row = u >> 3, q = u & 7;
        CPA16(b_u + (uint32_t)(row * SG_ROW + q * 4) * 4,
              W + (size_t)(n0 + row) * HH + kc + q * 4);
    }
    CPA_COMMIT();
}

__global__ void __launch_bounds__(256, 2) k_sg(const float* __restrict__ W,
                                               const float* __restrict__ bias) {
    __shared__ __align__(16) float sm[2 * SG_STAGE];
    const int tid  = threadIdx.x;
    const int lane = tid & 31, warp = tid >> 5;
    const int gid  = lane >> 2, tig = lane & 3;
    const int n0   = blockIdx.x * 128;

    float acc[2][2][4];
    #pragma unroll
    for (int a = 0; a < 2; a++)
        #pragma unroll
        for (int b = 0; b < 2; b++)
            #pragma unroll
            for (int c = 0; c < 4; c++) acc[a][b][c] = 0.f;

    sg_load(sm, 0, 0, W, n0, tid);
    sg_load(sm, 1, 1, W, n0, tid);

    for (int kt = 0; kt < 16; kt++) {
        const int s = kt & 1;
        if (kt < 15) { CPA_WAIT1(); } else { CPA_WAIT0(); }
        __syncthreads();

        const float* As = sm + s * SG_STAGE;
        const float* Bs = As + SG_ATILE;
        #pragma unroll
        for (int ks = 0; ks < 4; ks++) {
            const int kb = ks * 8;
            unsigned af[2][4];
            #pragma unroll
            for (int mt = 0; mt < 2; mt++) {
                int r = mt * 16 + gid;
                af[mt][0] = __float_as_uint(As[r * SG_ROW + kb + tig]);
                af[mt][1] = __float_as_uint(As[(r + 8) * SG_ROW + kb + tig]);
                af[mt][2] = __float_as_uint(As[r * SG_ROW + kb + tig + 4]);
                af[mt][3] = __float_as_uint(As[(r + 8) * SG_ROW + kb + tig + 4]);
            }
            #pragma unroll
            for (int nt = 0; nt < 2; nt++) {
                int c = warp * 16 + nt * 8 + gid;
                unsigned b0 = __float_as_uint(Bs[c * SG_ROW + kb + tig]);
                unsigned b1 = __float_as_uint(Bs[c * SG_ROW + kb + tig + 4]);
                mma_tf32(acc[0][nt], af[0], b0, b1);
                mma_tf32(acc[1][nt], af[1], b0, b1);
            }
        }
        __syncthreads();
        if (kt + 2 < 16)
            sg_load(sm, s, kt + 2, W, n0, tid);
    }

    #pragma unroll
    for (int mt = 0; mt < 2; mt++) {
        #pragma unroll
        for (int nt = 0; nt < 2; nt++) {
            int br = mt * 16 + gid;
            int c  = n0 + warp * 16 + nt * 8 + tig * 2;
            float bi0 = bias[c], bi1 = bias[c + 1];
            g_score_g[br * VV + c]           = acc[mt][nt][0] + bi0;
            g_score_g[br * VV + c + 1]       = acc[mt][nt][1] + bi1;
            g_score_g[(br + 8) * VV + c]     = acc[mt][nt][2] + bi0;
            g_score_g[(br + 8) * VV + c + 1] = acc[mt][nt][3] + bi1;
        }
    }
}

/* ------------- GRU gate combine ---------------------------------------- */
__global__ void k_gates(const float* __restrict__ prev, float* __restrict__ o_state) {
    int idx = blockIdx.x * blockDim.x + threadIdx.x;
    if (idx >= BB * HH) return;
    int b = idx >> 9, h = idx & (HH - 1);
    const float* gi = g_gi + b * H3;
    const float* gh = g_gh + b * H3;
    float r  = 1.f / (1.f + expf(-(gi[h] + gh[h])));
    float z  = 1.f / (1.f + expf(-(gi[HH + h] + gh[HH + h])));
    float nn = tanhf(gi[2 * HH + h] + r * gh[2 * HH + h]);
    float st = (1.f - z) * nn + z * prev[idx];
    g_state[idx] = st;
    o_state[idx] = st;
}

/* ------------- pass A: fp16 m16n8k16 mma + ldmatrix fragments ----------- */
__device__ __forceinline__ void pa_load(uint32_t* sm, int stage, int chunk,
                                        int m0, int n0, int tid) {
    uint32_t* As = sm + stage * PA_STAGE;
    uint32_t* Bs = As + PA_ATILE;
    const uint32_t a_u32 = smem_u32(As);
    const uint32_t b_u32 = smem_u32(Bs);
    const int kc = chunk * 64;           /* halves */
    #pragma unroll
    for (int j = 0; j < 4; j++) {
        int u = tid + j * 256;
        int row = u >> 3, q = u & 7;
        CPA16(a_u32 + (uint32_t)(row * PA_ROW + q * 4) * 4,
              g_ench + (size_t)(m0 + row) * 1024 + kc + q * 8);
        CPA16(b_u32 + (uint32_t)(row * PA_ROW + q * 4) * 4,
              g_wch + (size_t)(n0 + row) * 1024 + kc + q * 8);
    }
    CPA_COMMIT();
}

__global__ void __launch_bounds__(256, 2) k_passA(const float* __restrict__ Wcb,
                                                  const float* __restrict__ bin) {
    extern __shared__ __align__(16) uint32_t smu[];
    const int tid  = threadIdx.x;
    const int lane = tid & 31, warp = tid >> 5;
    const int gid  = lane >> 2, tig = lane & 3;
    const int wm   = warp & 3, wn = warp >> 2;        /* 4 x 2 warps */
    const int m0   = blockIdx.y * 128;
    const int n0   = blockIdx.x * 128;

    const uint32_t smb = smem_u32(smu);
    const int lrow8 = lane & 7;
    const int quad  = lane >> 3;

    /* ldmatrix static offsets (bytes, within a stage) */
    /* A x4 for mt: matrices {(r,kb),(r+8,kb),(r,kb+4),(r+8,kb+4)} */
    uint32_t aStat[2];
    #pragma unroll
    for (int mt = 0; mt < 2; mt++) {
        int aRow  = wm * 32 + mt * 16 + (quad & 1) * 8 + lrow8;
        int aColU = (quad >> 1) * 4;
        aStat[mt] = (uint32_t)(aRow * PA_ROW + aColU) * 4;
    }
    /* B x4 for group g: matrices {nt.b0, nt.b1, (nt+1).b0, (nt+1).b1}, nt=2g */
    uint32_t bStat[4];
    #pragma unroll
    for (int g = 0; g < 4; g++) {
        int bRow  = wn * 64 + (2 * g + (quad >> 1)) * 8 + lrow8;
        int bColU = (quad & 1) * 4;
        bStat[g] = (uint32_t)(PA_ATILE * 4) + (uint32_t)(bRow * PA_ROW + bColU) * 4;
    }

    float acc[2][8][4];
    #pragma unroll
    for (int a = 0; a < 2; a++)
        #pragma unroll
        for (int b = 0; b < 8; b++)
            #pragma unroll
            for (int c = 0; c < 4; c++) acc[a][b][c] = 0.f;

    pa_load(smu, 0, 0, m0, n0, tid);
    pa_load(smu, 1, 1, m0, n0, tid);

    for (int kt = 0; kt < 16; kt++) {
        const int s = kt & 1;
        if (kt < 15) { CPA_WAIT1(); } else { CPA_WAIT0(); }
        __syncthreads();

        const uint32_t stageBase = smb + (uint32_t)(s * PA_STAGE) * 4;
        #pragma unroll
        for (int ks = 0; ks < 4; ks++) {
            const uint32_t kOff = (uint32_t)(ks * 8) * 4;   /* kb*4 bytes */
            unsigned af[2][4];
            LDM_X4(af[0][0], af[0][1], af[0][2], af[0][3], stageBase + aStat[0] + kOff);
            LDM_X4(af[1][0], af[1][1], af[1][2], af[1][3], stageBase + aStat[1] + kOff);
            unsigned bfr[16];
            LDM_X4(bfr[0],  bfr[1],  bfr[2],  bfr[3],  stageBase + bStat[0] + kOff);
            LDM_X4(bfr[4],  bfr[5],  bfr[6],  bfr[7],  stageBase + bStat[1] + kOff);
            LDM_X4(bfr[8],  bfr[9],  bfr[10], bfr[11], stageBase + bStat[2] + kOff);
            LDM_X4(bfr[12], bfr[13], bfr[14], bfr[15], stageBase + bStat[3] + kOff);
            #pragma unroll
            for (int nt = 0; nt < 8; nt++) {
                mma_f16(acc[0][nt], af[0], bfr[2 * nt], bfr[2 * nt + 1]);
                mma_f16(acc[1][nt], af[1], bfr[2 * nt], bfr[2 * nt + 1]);
            }
        }
        __syncthreads();
        if (kt + 2 < 16)
            pa_load(smu, s, kt + 2, m0, n0, tid);
    }

    /* epilogue: rank-1 + bias, tanh, multiply by state, reduce over h */
    const int bidx = m0 >> 10;
    const float* st = g_state + bidx * HH;
    #pragma unroll
    for (int mt = 0; mt < 2; mt++) {
        int rg = m0 + wm * 32 + mt * 16 + gid;
        float b0v = bin[rg], b1v = bin[rg + 8];
        float p0 = 0.f, p1 = 0.f;
        #pragma unroll
        for (int nt = 0; nt < 8; nt++) {
            int c0 = n0 + wn * 64 + nt * 8 + tig * 2;
            float ws0 = g_wsum[c0], ws1 = g_wsum[c0 + 1];
            float bb0 = Wcb[c0],    bb1 = Wcb[c0 + 1];
            float s0  = st[c0],     s1  = st[c0 + 1];
            p0 += tanh_fast(acc[mt][nt][0] + b0v * ws0 + bb0) * s0
                + tanh_fast(acc[mt][nt][1] + b0v * ws1 + bb1) * s1;
            p1 += tanh_fast(acc[mt][nt][2] + b1v * ws0 + bb0) * s0
                + tanh_fast(acc[mt][nt][3] + b1v * ws1 + bb1) * s1;
        }
        p0 += __shfl_xor_sync(0xffffffffu, p0, 1);
        p0 += __shfl_xor_sync(0xffffffffu, p0, 2);
        p1 += __shfl_xor_sync(0xffffffffu, p1, 1);
        p1 += __shfl_xor_sync(0xffffffffu, p1, 2);
        if (tig == 0) {
            atomicAdd(&g_score_c[rg], p0);
            atomicAdd(&g_score_c[rg + 8], p1);
        }
    }
}

/* ------------- finalize score_c: tanh + mask --------------------------- */
__global__ void k_fin(const int* __restrict__ eidx) {
    int m = blockIdx.x * blockDim.x + threadIdx.x;
    if (m >= MM) return;
    float v = tanhf(g_score_c[m]);
    if (eidx[m] == 0) v -= 1000.f;
    g_score_c[m] = v;
}

/* ------------- per-row softmax stats (1024 threads) --------------------- */
__global__ void __launch_bounds__(1024) k_rowstats() {
    __shared__ float red[1024];
    const int b = blockIdx.x, tid = threadIdx.x;
    const float* sg = g_score_g + b * VV;
    const float* sc = g_score_c + b * SS;
    float mx = -1e30f;
    for (int i = tid; i < VV; i += 1024) mx = fmaxf(mx, sg[i]);
    for (int i = tid; i < SS; i += 1024) mx = fmaxf(mx, sc[i]);
    red[tid] = mx; __syncthreads();
    for (int o = 512; o; o >>= 1) { if (tid < o) red[tid] = fmaxf(red[tid], red[tid + o]); __syncthreads(); }
    mx = red[0]; __syncthreads();

    float zg = 0.f;
    for (int i = tid; i < VV; i += 1024) zg += expf(sg[i] - mx);
    float zc = 0.f;
    for (int i = tid; i < SS; i += 1024) zc += expf(sc[i] - mx);
    red[tid] = zg + zc; __syncthreads();
    for (int o = 512; o; o >>= 1) { if (tid < o) red[tid] += red[tid + o]; __syncthreads(); }
    float Z = red[0]; __syncthreads();
    red[tid] = zc; __syncthreads();
    for (int o = 512; o; o >>= 1) { if (tid < o) red[tid] += red[tid + o]; __syncthreads(); }
    if (tid == 0) { g_max[b] = mx; g_Z[b] = Z; g_Sc[b] = red[0]; }
}

__global__ void k_compC() {
    int t = threadIdx.x;
    float v = (t < BB) ? g_Sc[t] / g_Z[t] : 0.f;
    #pragma unroll
    for (int o = 16; o; o >>= 1) v += __shfl_xor_sync(0xffffffffu, v, o);
    if (t == 0) g_C[0] = v;
}

/* ------------- output: base probs -------------------------------------- */
__global__ void k_outbase(float* __restrict__ o_out) {
    int i = blockIdx.x * blockDim.x + threadIdx.x;
    if (i >= BB * VO) return;
    int b = i / VO, v = i - b * VO;
    o_out[i] = (v < VV) ? expf(g_score_g[b * VV + v] - g_max[b]) / g_Z[b] : 1e-4f;
}

/* ------------- output: scatter-add prob_c ------------------------------- */
__global__ void k_scatter(const int* __restrict__ eidx, float* __restrict__ o_out) {
    int m = blockIdx.x * blockDim.x + threadIdx.x;
    if (m >= MM) return;
    int b = m >> 10;
    float p = expf(g_score_c[m] - g_max[b]) / g_Z[b];
    atomicAdd(o_out + b * VO + eidx[m], p);
}

/* ------------- weighted_out (sparse attn over idx matches) -------------- */
__global__ void k_weighted(const int* __restrict__ input_idx,
                           const int* __restrict__ eidx,
                           const float* __restrict__ encoded,
                           const float* __restrict__ bin,
                           float* __restrict__ o_w) {
    __shared__ int cnt;
    __shared__ int sl[SS];
    __shared__ float av[SS];
    const int b = blockIdx.x, tid = threadIdx.x;
    if (tid == 0) cnt = 0;
    __syncthreads();
    int target = input_idx[b];
    for (int s = tid; s < SS; s += 256)
        if (eidx[b * SS + s] == target) { int p = atomicAdd(&cnt, 1); sl[p] = s; }
    __syncthreads();
    int n = cnt;
    float scale = (n > 1) ? 1.f / (float)n : 1.f;
    for (int i = tid; i < n; i += 256) {
        int s = sl[i];
        float pc = expf(g_score_c[b * SS + s] - g_max[b]) / g_Z[b];
        av[i] = pc / g_C[0] * scale;
    }
    __syncthreads();
    for (int d = tid; d < DD2; d += 256) {
        float acc = 0.f;
        for (int i = 0; i < n; i++) {
            int s = sl[i];
            float e = (d < 2 * HH) ? encoded[(size_t)(b * SS + s) * (2 * HH) + d]
                                   : bin[b * SS + s];
            acc += av[i] * e;
        }
        o_w[b * DD2 + d] = acc;
    }
}

/* ======================= host launcher ================================== */
extern "C" void kernel_launch(void* const* d_in, const int* in_sizes, int n_in,
                              void* d_out, int out_size) {
    const int*   input_idx = (const int*)  d_in[0];
    const float* encoded   = (const float*)d_in[1];
    const int*   eidx      = (const int*)  d_in[2];
    const float* prev      = (const float*)d_in[3];
    const float* weighted  = (const float*)d_in[4];
    const float* bin       = (const float*)d_in[5];
    /* d_in[6] = order (always 1) */
    const float* embed     = (const float*)d_in[7];
    const float* W_ih      = (const float*)d_in[8];
    const float* b_ih      = (const float*)d_in[9];
    const float* W_hh      = (const float*)d_in[10];
    const float* b_hh      = (const float*)d_in[11];
    const float* Wo_w      = (const float*)d_in[12];
    const float* Wo_b      = (const float*)d_in[13];
    const float* Wc_w      = (const float*)d_in[14];
    const float* Wc_b      = (const float*)d_in[15];

    float* o_out   = (float*)d_out;
    float* o_state = o_out + (size_t)BB * VO;
    float* o_w     = o_state + (size_t)BB * HH;

    cudaFuncSetAttribute(k_passA, cudaFuncAttributeMaxDynamicSharedMemorySize,
                         PA_SMEM);

    {
        size_t tot = CV_ENC4 + CV_WC4;
        k_conv<<<(unsigned)((tot + 255) / 256), 256>>>(encoded, Wc_w);
    }
    int prep_n = BB * ININ + HH + MM;
    k_prep<<<(prep_n + 255) / 256, 256>>>(input_idx, embed, weighted, Wc_w);
    k_gru<<<48, 256>>>(W_ih, b_ih, W_hh, b_hh, prev);
    k_gates<<<(BB * HH + 255) / 256, 256>>>(prev, o_state);
    k_sg<<<VV / 128, 256>>>(Wo_w, Wo_b);
    {
        dim3 grid(HH / 128, MM / 128);   /* n fastest */
        k_passA<<<grid, 256, PA_SMEM>>>(Wc_b, bin);
    }
    k_fin<<<MM / 256, 256>>>(eidx);
    k_rowstats<<<BB, 1024>>>();
    k_compC<<<1, 32>>>();
    k_outbase<<<(BB * VO + 255) / 256, 256>>>(o_out);
    k_scatter<<<MM / 256, 256>>>(eidx, o_out);
    k_weighted<<<BB, 256>>>(input_idx, eidx, encoded, bin, o_w);
}

// round 16
// speedup vs baseline: 1.8975x; 1.0181x over previous
#include <cuda_runtime.h>
#include <cuda_fp16.h>
#include <math.h>
#include <stdint.h>

#define BB    32
#define SS    1024
#define VV    32000
#define EE    256
#define HH    512
#define OOV   12
#define DD2   1124
#define ININ  1380
#define MM    (BB*SS)
#define VO    (VV+OOV)
#define H3    (3*HH)

/* ------------- device scratch (no allocation allowed) ------------------ */
__device__ float g_x[BB*ININ];
__device__ float g_wsum[HH];
__device__ float g_gi[BB*H3];
__device__ float g_gh[BB*H3];
__device__ float g_state[BB*HH];
__device__ float g_score_g[BB*VV];
__device__ float g_score_c[MM];
__device__ float g_max[BB], g_Z[BB], g_Sc[BB], g_C[1];
__device__ __half g_ench[(size_t)MM*1024];   /* enc[:, :1024] in fp16 */
__device__ __half g_wch[HH*1024];            /* Wc[:, :1024] in fp16  */

/* ------------- helpers ------------------------------------------------- */
__device__ __forceinline__ float tanh_fast(float x) {
    float y;
    asm("tanh.approx.f32 %0, %1;" : "=f"(y) : "f"(x));
    return y;
}
__device__ __forceinline__ uint32_t smem_u32(const void* p) {
    uint32_t a;
    asm("{ .reg .u64 t; cvta.to.shared.u64 t, %1; cvt.u32.u64 %0, t; }"
        : "=r"(a) : "l"(p));
    return a;
}
__device__ __forceinline__ void mma_tf32(float* d, const unsigned* a,
                                         unsigned b0, unsigned b1) {
    asm volatile(
        "mma.sync.aligned.m16n8k8.row.col.f32.tf32.tf32.f32 "
        "{%0,%1,%2,%3}, {%4,%5,%6,%7}, {%8,%9}, {%0,%1,%2,%3};\n"
        : "+f"(d[0]), "+f"(d[1]), "+f"(d[2]), "+f"(d[3])
        : "r"(a[0]), "r"(a[1]), "r"(a[2]), "r"(a[3]), "r"(b0), "r"(b1));
}
__device__ __forceinline__ void mma_f16(float* d, const unsigned* a,
                                        unsigned b0, unsigned b1) {
    asm volatile(
        "mma.sync.aligned.m16n8k16.row.col.f32.f16.f16.f32 "
        "{%0,%1,%2,%3}, {%4,%5,%6,%7}, {%8,%9}, {%0,%1,%2,%3};\n"
        : "+f"(d[0]), "+f"(d[1]), "+f"(d[2]), "+f"(d[3])
        : "r"(a[0]), "r"(a[1]), "r"(a[2]), "r"(a[3]), "r"(b0), "r"(b1));
}
#define LDM_X4(r0, r1, r2, r3, addr) \
    asm volatile("ldmatrix.sync.aligned.m8n8.x4.shared.b16 {%0,%1,%2,%3}, [%4];" \
                 : "=r"(r0), "=r"(r1), "=r"(r2), "=r"(r3) : "r"(addr))

#define CPA16(dst, src) \
    asm volatile("cp.async.cg.shared.global [%0], [%1], 16;" \
                 :: "r"(dst), "l"(src) : "memory")
#define CPA_COMMIT()  asm volatile("cp.async.commit_group;" ::: "memory")
#define CPA_WAIT1()   asm volatile("cp.async.wait_group 1;" ::: "memory")
#define CPA_WAIT0()   asm volatile("cp.async.wait_group 0;" ::: "memory")

/* passA smem (fp16): 2 stages x (A 128x36 + B 128x36) uint32 */
#define PA_ROW     36
#define PA_ATILE   (128*PA_ROW)
#define PA_STAGE   (2*PA_ATILE)
#define PA_SMEM_U  (2*PA_STAGE)
#define PA_SMEM    (PA_SMEM_U*4)         /* 73728 bytes */

/* k_sg smem: 2 stages x (A 32x36 + B 128x36) floats = 46080 B */
#define SG_ROW     36
#define SG_ATILE   (32*SG_ROW)
#define SG_BTILE   (128*SG_ROW)
#define SG_STAGE   (SG_ATILE + SG_BTILE)

/* ------------- fp16 conversion: enc[:, :1024] and Wc[:, :1024] --------- */
#define CV_ENC4 ((size_t)MM*1024/4)
#define CV_WC4  (HH*1024/4)
__global__ void k_conv(const float* __restrict__ enc,
                       const float* __restrict__ Wc) {
    size_t i = (size_t)blockIdx.x * blockDim.x + threadIdx.x;
    if (i < CV_ENC4) {
        float4 v = ((const float4*)enc)[i];
        __half2* dst = (__half2*)g_ench + i * 2;
        dst[0] = __floats2half2_rn(v.x, v.y);
        dst[1] = __floats2half2_rn(v.z, v.w);
    } else if (i < CV_ENC4 + CV_WC4) {
        size_t j = i - CV_ENC4;
        int row = (int)(j >> 8), c4 = (int)(j & 255);
        float4 v = *(const float4*)(Wc + (size_t)row * DD2 + c4 * 4);
        __half2* dst = (__half2*)(g_wch + row * 1024 + c4 * 4);
        dst[0] = __floats2half2_rn(v.x, v.y);
        dst[1] = __floats2half2_rn(v.z, v.w);
    }
}

/* ------------- prep: x=[emb|weighted], wsum, zero score_c -------------- */
__global__ void k_prep(const int* __restrict__ input_idx,
                       const float* __restrict__ embed,
                       const float* __restrict__ weighted,
                       const float* __restrict__ Wc) {
    int i = blockIdx.x * blockDim.x + threadIdx.x;
    if (i < BB * ININ) {
        int b = i / ININ, j = i - b * ININ;
        g_x[i] = (j < EE) ? embed[input_idx[b] * EE + j]
                          : weighted[b * DD2 + (j - EE)];
    } else if (i < BB * ININ + HH) {
        int h = i - BB * ININ;
        float s = 0.f;
        #pragma unroll 4
        for (int j = 0; j < 100; j++) s += Wc[h * DD2 + 2 * HH + j];
        g_wsum[h] = s;
    } else if (i < BB * ININ + HH + MM) {
        g_score_c[i - BB * ININ - HH] = 0.f;
    }
}

/* ------------- generic small-N SIMT GEMM core -------------------------- */
template<int RP>
__device__ __forceinline__ void gemm_core(float (*Ws)[33], float (*Xs)[33], int r0,
                                          const float* __restrict__ W, int ldw,
                                          const float* __restrict__ X, int ldx,
                                          const float* __restrict__ bias,
                                          float* __restrict__ out, int ldo, int K) {
    const int tid = threadIdx.x;
    const int vi  = tid & 31, bi = tid >> 5;
    float acc[RP][4];
    #pragma unroll
    for (int p = 0; p < RP; p++)
        #pragma unroll
        for (int q = 0; q < 4; q++) acc[p][q] = 0.f;

    for (int kc = 0; kc < K; kc += 32) {
        for (int e = tid; e < RP * 32 * 32; e += 256) {
            int row = e >> 5, k = e & 31;
            Ws[row][k] = (kc + k < K) ? W[(r0 + row) * ldw + kc + k] : 0.f;
        }
        for (int e = tid; e < 32 * 32; e += 256) {
            int row = e >> 5, k = e & 31;
            Xs[row][k] = (kc + k < K) ? X[row * ldx + kc + k] : 0.f;
        }
        __syncthreads();
        #pragma unroll
        for (int k = 0; k < 32; k++) {
            float x[4];
            #pragma unroll
            for (int q = 0; q < 4; q++) x[q] = Xs[bi * 4 + q][k];
            #pragma unroll
            for (int p = 0; p < RP; p++) {
                float w = Ws[vi + 32 * p][k];
                #pragma unroll
                for (int q = 0; q < 4; q++) acc[p][q] += w * x[q];
            }
        }
        __syncthreads();
    }
    #pragma unroll
    for (int p = 0; p < RP; p++) {
        int r = r0 + vi + 32 * p;
        float bv = bias[r];
        #pragma unroll
        for (int q = 0; q < 4; q++)
            out[(bi * 4 + q) * ldo + r] = acc[p][q] + bv;
    }
}

/* merged GRU input/hidden GEMMs */
__global__ void __launch_bounds__(256) k_gru(const float* __restrict__ W_ih,
                                             const float* __restrict__ b_ih,
                                             const float* __restrict__ W_hh,
                                             const float* __restrict__ b_hh,
                                             const float* __restrict__ prev) {
    __shared__ float Ws[64][33]; __shared__ float Xs[32][33];
    if (blockIdx.x < 24)
        gemm_core<2>(Ws, Xs, blockIdx.x * 64, W_ih, ININ, g_x, ININ, b_ih, g_gi, H3, ININ);
    else
        gemm_core<2>(Ws, Xs, (blockIdx.x - 24) * 64, W_hh, HH, prev, HH, b_hh, g_gh, H3, HH);
}

/* ------------- score_g: tf32 mma streaming GEMM ------------------------ */
__device__ __forceinline__ void sg_load(float* sm, int stage, int chunk,
                                        const float* __restrict__ W,
                                        int n0, int tid) {
    float* As = sm + stage * SG_STAGE;
    float* Bs = As + SG_ATILE;
    const uint32_t a_u = smem_u32(As);
    const uint32_t b_u = smem_u32(Bs);
    const int kc = chunk * 32;
    {
        int row = tid >> 3, q = tid & 7;
        CPA16(a_u + (uint32_t)(row * SG_ROW + q * 4) * 4,
              g_state + row * HH + kc + q * 4);
    }
    #pragma unroll
    for (int j = 0; j < 4; j++) {
        int u = tid + j * 256;
        int row = u >> 3, q = u & 7;
        CPA16(b_u + (uint32_t)(row * SG_ROW + q * 4) * 4,
              W + (size_t)(n0 + row) * HH + kc + q * 4);
    }
    CPA_COMMIT();
}

__global__ void __launch_bounds__(256, 2) k_sg(const float* __restrict__ W,
                                               const float* __restrict__ bias) {
    __shared__ __align__(16) float sm[2 * SG_STAGE];
    const int tid  = threadIdx.x;
    const int lane = tid & 31, warp = tid >> 5;
    const int gid  = lane >> 2, tig = lane & 3;
    const int n0   = blockIdx.x * 128;

    float acc[2][2][4];
    #pragma unroll
    for (int a = 0; a < 2; a++)
        #pragma unroll
        for (int b = 0; b < 2; b++)
            #pragma unroll
            for (int c = 0; c < 4; c++) acc[a][b][c] = 0.f;

    sg_load(sm, 0, 0, W, n0, tid);
    sg_load(sm, 1, 1, W, n0, tid);

    for (int kt = 0; kt < 16; kt++) {
        const int s = kt & 1;
        if (kt < 15) { CPA_WAIT1(); } else { CPA_WAIT0(); }
        __syncthreads();

        const float* As = sm + s * SG_STAGE;
        const float* Bs = As + SG_ATILE;
        #pragma unroll
        for (int ks = 0; ks < 4; ks++) {
            const int kb = ks * 8;
            unsigned af[2][4];
            #pragma unroll
            for (int mt = 0; mt < 2; mt++) {
                int r = mt * 16 + gid;
                af[mt][0] = __float_as_uint(As[r * SG_ROW + kb + tig]);
                af[mt][1] = __float_as_uint(As[(r + 8) * SG_ROW + kb + tig]);
                af[mt][2] = __float_as_uint(As[r * SG_ROW + kb + tig + 4]);
                af[mt][3] = __float_as_uint(As[(r + 8) * SG_ROW + kb + tig + 4]);
            }
            #pragma unroll
            for (int nt = 0; nt < 2; nt++) {
                int c = warp * 16 + nt * 8 + gid;
                unsigned b0 = __float_as_uint(Bs[c * SG_ROW + kb + tig]);
                unsigned b1 = __float_as_uint(Bs[c * SG_ROW + kb + tig + 4]);
                mma_tf32(acc[0][nt], af[0], b0, b1);
                mma_tf32(acc[1][nt], af[1], b0, b1);
            }
        }
        __syncthreads();
        if (kt + 2 < 16)
            sg_load(sm, s, kt + 2, W, n0, tid);
    }

    #pragma unroll
    for (int mt = 0; mt < 2; mt++) {
        #pragma unroll
        for (int nt = 0; nt < 2; nt++) {
            int br = mt * 16 + gid;
            int c  = n0 + warp * 16 + nt * 8 + tig * 2;
            float bi0 = bias[c], bi1 = bias[c + 1];
            g_score_g[br * VV + c]           = acc[mt][nt][0] + bi0;
            g_score_g[br * VV + c + 1]       = acc[mt][nt][1] + bi1;
            g_score_g[(br + 8) * VV + c]     = acc[mt][nt][2] + bi0;
            g_score_g[(br + 8) * VV + c + 1] = acc[mt][nt][3] + bi1;
        }
    }
}

/* ------------- GRU gate combine ---------------------------------------- */
__global__ void k_gates(const float* __restrict__ prev, float* __restrict__ o_state) {
    int idx = blockIdx.x * blockDim.x + threadIdx.x;
    if (idx >= BB * HH) return;
    int b = idx >> 9, h = idx & (HH - 1);
    const float* gi = g_gi + b * H3;
    const float* gh = g_gh + b * H3;
    float r  = 1.f / (1.f + expf(-(gi[h] + gh[h])));
    float z  = 1.f / (1.f + expf(-(gi[HH + h] + gh[HH + h])));
    float nn = tanhf(gi[2 * HH + h] + r * gh[2 * HH + h]);
    float st = (1.f - z) * nn + z * prev[idx];
    g_state[idx] = st;
    o_state[idx] = st;
}

/* ------------- pass A: fp16 m16n8k16 mma + ldmatrix fragments ----------- */
__device__ __forceinline__ void pa_load(uint32_t* sm, int stage, int chunk,
                                        int m0, int n0, int tid) {
    uint32_t* As = sm + stage * PA_STAGE;
    uint32_t* Bs = As + PA_ATILE;
    const uint32_t a_u32 = smem_u32(As);
    const uint32_t b_u32 = smem_u32(Bs);
    const int kc = chunk * 64;           /* halves */
    #pragma unroll
    for (int j = 0; j < 4; j++) {
        int u = tid + j * 256;
        int row = u >> 3, q = u & 7;
        CPA16(a_u32 + (uint32_t)(row * PA_ROW + q * 4) * 4,
              g_ench + (size_t)(m0 + row) * 1024 + kc + q * 8);
        CPA16(b_u32 + (uint32_t)(row * PA_ROW + q * 4) * 4,
              g_wch + (size_t)(n0 + row) * 1024 + kc + q * 8);
    }
    CPA_COMMIT();
}

__global__ void __launch_bounds__(256, 2) k_passA(const float* __restrict__ Wcb,
                                                  const float* __restrict__ bin) {
    extern __shared__ __align__(16) uint32_t smu[];
    const int tid  = threadIdx.x;
    const int lane = tid & 31, warp = tid >> 5;
    const int gid  = lane >> 2, tig = lane & 3;
    const int wm   = warp & 3, wn = warp >> 2;        /* 4 x 2 warps */
    const int m0   = blockIdx.y * 128;
    const int n0   = blockIdx.x * 128;

    const uint32_t smb = smem_u32(smu);
    const int lrow8 = lane & 7;
    const int quad  = lane >> 3;

    uint32_t aStat[2];
    #pragma unroll
    for (int mt = 0; mt < 2; mt++) {
        int aRow  = wm * 32 + mt * 16 + (quad & 1) * 8 + lrow8;
        int aColU = (quad >> 1) * 4;
        aStat[mt] = (uint32_t)(aRow * PA_ROW + aColU) * 4;
    }
    uint32_t bStat[4];
    #pragma unroll
    for (int g = 0; g < 4; g++) {
        int bRow  = wn * 64 + (2 * g + (quad >> 1)) * 8 + lrow8;
        int bColU = (quad & 1) * 4;
        bStat[g] = (uint32_t)(PA_ATILE * 4) + (uint32_t)(bRow * PA_ROW + bColU) * 4;
    }

    float acc[2][8][4];
    #pragma unroll
    for (int a = 0; a < 2; a++)
        #pragma unroll
        for (int b = 0; b < 8; b++)
            #pragma unroll
            for (int c = 0; c < 4; c++) acc[a][b][c] = 0.f;

    pa_load(smu, 0, 0, m0, n0, tid);
    pa_load(smu, 1, 1, m0, n0, tid);

    for (int kt = 0; kt < 16; kt++) {
        const int s = kt & 1;
        if (kt < 15) { CPA_WAIT1(); } else { CPA_WAIT0(); }
        __syncthreads();

        const uint32_t stageBase = smb + (uint32_t)(s * PA_STAGE) * 4;
        #pragma unroll
        for (int ks = 0; ks < 4; ks++) {
            const uint32_t kOff = (uint32_t)(ks * 8) * 4;
            unsigned af[2][4];
            LDM_X4(af[0][0], af[0][1], af[0][2], af[0][3], stageBase + aStat[0] + kOff);
            LDM_X4(af[1][0], af[1][1], af[1][2], af[1][3], stageBase + aStat[1] + kOff);
            unsigned bfr[16];
            LDM_X4(bfr[0],  bfr[1],  bfr[2],  bfr[3],  stageBase + bStat[0] + kOff);
            LDM_X4(bfr[4],  bfr[5],  bfr[6],  bfr[7],  stageBase + bStat[1] + kOff);
            LDM_X4(bfr[8],  bfr[9],  bfr[10], bfr[11], stageBase + bStat[2] + kOff);
            LDM_X4(bfr[12], bfr[13], bfr[14], bfr[15], stageBase + bStat[3] + kOff);
            #pragma unroll
            for (int nt = 0; nt < 8; nt++) {
                mma_f16(acc[0][nt], af[0], bfr[2 * nt], bfr[2 * nt + 1]);
                mma_f16(acc[1][nt], af[1], bfr[2 * nt], bfr[2 * nt + 1]);
            }
        }
        __syncthreads();
        if (kt + 2 < 16)
            pa_load(smu, s, kt + 2, m0, n0, tid);
    }

    /* epilogue: rank-1 + bias, tanh, multiply by state, reduce over h */
    const int bidx = m0 >> 10;
    const float* st = g_state + bidx * HH;
    #pragma unroll
    for (int mt = 0; mt < 2; mt++) {
        int rg = m0 + wm * 32 + mt * 16 + gid;
        float b0v = bin[rg], b1v = bin[rg + 8];
        float p0 = 0.f, p1 = 0.f;
        #pragma unroll
        for (int nt = 0; nt < 8; nt++) {
            int c0 = n0 + wn * 64 + nt * 8 + tig * 2;
            float ws0 = g_wsum[c0], ws1 = g_wsum[c0 + 1];
            float bb0 = Wcb[c0],    bb1 = Wcb[c0 + 1];
            float s0  = st[c0],     s1  = st[c0 + 1];
            p0 += tanh_fast(acc[mt][nt][0] + b0v * ws0 + bb0) * s0
                + tanh_fast(acc[mt][nt][1] + b0v * ws1 + bb1) * s1;
            p1 += tanh_fast(acc[mt][nt][2] + b1v * ws0 + bb0) * s0
                + tanh_fast(acc[mt][nt][3] + b1v * ws1 + bb1) * s1;
        }
        p0 += __shfl_xor_sync(0xffffffffu, p0, 1);
        p0 += __shfl_xor_sync(0xffffffffu, p0, 2);
        p1 += __shfl_xor_sync(0xffffffffu, p1, 1);
        p1 += __shfl_xor_sync(0xffffffffu, p1, 2);
        if (tig == 0) {
            atomicAdd(&g_score_c[rg], p0);
            atomicAdd(&g_score_c[rg + 8], p1);
        }
    }
}

/* ------------- finalize score_c: tanh + mask --------------------------- */
__global__ void k_fin(const int* __restrict__ eidx) {
    int m = blockIdx.x * blockDim.x + threadIdx.x;
    if (m >= MM) return;
    float v = tanhf(g_score_c[m]);
    if (eidx[m] == 0) v -= 1000.f;
    g_score_c[m] = v;
}

/* ------------- per-row softmax stats (1024 threads) --------------------- */
__global__ void __launch_bounds__(1024) k_rowstats() {
    __shared__ float red[1024];
    const int b = blockIdx.x, tid = threadIdx.x;
    const float* sg = g_score_g + b * VV;
    const float* sc = g_score_c + b * SS;
    float mx = -1e30f;
    for (int i = tid; i < VV; i += 1024) mx = fmaxf(mx, sg[i]);
    for (int i = tid; i < SS; i += 1024) mx = fmaxf(mx, sc[i]);
    red[tid] = mx; __syncthreads();
    for (int o = 512; o; o >>= 1) { if (tid < o) red[tid] = fmaxf(red[tid], red[tid + o]); __syncthreads(); }
    mx = red[0]; __syncthreads();

    float zg = 0.f;
    for (int i = tid; i < VV; i += 1024) zg += expf(sg[i] - mx);
    float zc = 0.f;
    for (int i = tid; i < SS; i += 1024) zc += expf(sc[i] - mx);
    red[tid] = zg + zc; __syncthreads();
    for (int o = 512; o; o >>= 1) { if (tid < o) red[tid] += red[tid + o]; __syncthreads(); }
    float Z = red[0]; __syncthreads();
    red[tid] = zc; __syncthreads();
    for (int o = 512; o; o >>= 1) { if (tid < o) red[tid] += red[tid + o]; __syncthreads(); }
    if (tid == 0) { g_max[b] = mx; g_Z[b] = Z; g_Sc[b] = red[0]; }
}

__global__ void k_compC() {
    int t = threadIdx.x;
    float v = (t < BB) ? g_Sc[t] / g_Z[t] : 0.f;
    #pragma unroll
    for (int o = 16; o; o >>= 1) v += __shfl_xor_sync(0xffffffffu, v, o);
    if (t == 0) g_C[0] = v;
}

/* ------------- output: base probs -------------------------------------- */
__global__ void k_outbase(float* __restrict__ o_out) {
    int i = blockIdx.x * blockDim.x + threadIdx.x;
    if (i >= BB * VO) return;
    int b = i / VO, v = i - b * VO;
    o_out[i] = (v < VV) ? expf(g_score_g[b * VV + v] - g_max[b]) / g_Z[b] : 1e-4f;
}

/* ------------- output: scatter-add prob_c ------------------------------- */
__global__ void k_scatter(const int* __restrict__ eidx, float* __restrict__ o_out) {
    int m = blockIdx.x * blockDim.x + threadIdx.x;
    if (m >= MM) return;
    int b = m >> 10;
    float p = expf(g_score_c[m] - g_max[b]) / g_Z[b];
    atomicAdd(o_out + b * VO + eidx[m], p);
}

/* ------------- weighted_out (sparse attn over idx matches) -------------- */
__global__ void k_weighted(const int* __restrict__ input_idx,
                           const int* __restrict__ eidx,
                           const float* __restrict__ encoded,
                           const float* __restrict__ bin,
                           float* __restrict__ o_w) {
    __shared__ int cnt;
    __shared__ int sl[SS];
    __shared__ float av[SS];
    const int b = blockIdx.x, tid = threadIdx.x;
    if (tid == 0) cnt = 0;
    __syncthreads();
    int target = input_idx[b];
    for (int s = tid; s < SS; s += 256)
        if (eidx[b * SS + s] == target) { int p = atomicAdd(&cnt, 1); sl[p] = s; }
    __syncthreads();
    int n = cnt;
    float scale = (n > 1) ? 1.f / (float)n : 1.f;
    for (int i = tid; i < n; i += 256) {
        int s = sl[i];
        float pc = expf(g_score_c[b * SS + s] - g_max[b]) / g_Z[b];
        av[i] = pc / g_C[0] * scale;
    }
    __syncthreads();
    for (int d = tid; d < DD2; d += 256) {
        float acc = 0.f;
        for (int i = 0; i < n; i++) {
            int s = sl[i];
            float e = (d < 2 * HH) ? encoded[(size_t)(b * SS + s) * (2 * HH) + d]
                                   : bin[b * SS + s];
            acc += av[i] * e;
        }
        o_w[b * DD2 + d] = acc;
    }
}

/* ======================= host launcher ================================== */
extern "C" void kernel_launch(void* const* d_in, const int* in_sizes, int n_in,
                              void* d_out, int out_size) {
    const int*   input_idx = (const int*)  d_in[0];
    const float* encoded   = (const float*)d_in[1];
    const int*   eidx      = (const int*)  d_in[2];
    const float* prev      = (const float*)d_in[3];
    const float* weighted  = (const float*)d_in[4];
    const float* bin       = (const float*)d_in[5];
    /* d_in[6] = order (always 1) */
    const float* embed     = (const float*)d_in[7];
    const float* W_ih      = (const float*)d_in[8];
    const float* b_ih      = (const float*)d_in[9];
    const float* W_hh      = (const float*)d_in[10];
    const float* b_hh      = (const float*)d_in[11];
    const float* Wo_w      = (const float*)d_in[12];
    const float* Wo_b      = (const float*)d_in[13];
    const float* Wc_w      = (const float*)d_in[14];
    const float* Wc_b      = (const float*)d_in[15];

    float* o_out   = (float*)d_out;
    float* o_state = o_out + (size_t)BB * VO;
    float* o_w     = o_state + (size_t)BB * HH;

    static cudaStream_t s2 = 0;
    static cudaEvent_t eFork = 0, eConv = 0, eGates = 0, eSg = 0;
    if (!s2) {
        cudaStreamCreateWithFlags(&s2, cudaStreamNonBlocking);
        cudaEventCreateWithFlags(&eFork,  cudaEventDisableTiming);
        cudaEventCreateWithFlags(&eConv,  cudaEventDisableTiming);
        cudaEventCreateWithFlags(&eGates, cudaEventDisableTiming);
        cudaEventCreateWithFlags(&eSg,    cudaEventDisableTiming);
        cudaFuncSetAttribute(k_passA, cudaFuncAttributeMaxDynamicSharedMemorySize,
                             PA_SMEM);
    }

    /* fork: conversion stream */
    cudaEventRecord(eFork, 0);
    cudaStreamWaitEvent(s2, eFork, 0);
    {
        size_t tot = CV_ENC4 + CV_WC4;
        k_conv<<<(unsigned)((tot + 255) / 256), 256, 0, s2>>>(encoded, Wc_w);
    }
    cudaEventRecord(eConv, s2);

    /* main: GRU chain */
    int prep_n = BB * ININ + HH + MM;
    k_prep<<<(prep_n + 255) / 256, 256>>>(input_idx, embed, weighted, Wc_w);
    k_gru<<<48, 256>>>(W_ih, b_ih, W_hh, b_hh, prev);
    k_gates<<<(BB * HH + 255) / 256, 256>>>(prev, o_state);
    cudaEventRecord(eGates, 0);

    /* s2: score_g GEMM (needs g_state) runs concurrent with passA */
    cudaStreamWaitEvent(s2, eGates, 0);
    k_sg<<<VV / 128, 256, 0, s2>>>(Wo_w, Wo_b);
    cudaEventRecord(eSg, s2);

    /* main: passA (needs conversion) */
    cudaStreamWaitEvent(0, eConv, 0);
    {
        dim3 grid(HH / 128, MM / 128);   /* n fastest */
        k_passA<<<grid, 256, PA_SMEM>>>(Wc_b, bin);
    }
    k_fin<<<MM / 256, 256>>>(eidx);

    /* join: rowstats needs score_g (s2) and score_c (main) */
    cudaStreamWaitEvent(0, eSg, 0);
    k_rowstats<<<BB, 1024>>>();
    k_compC<<<1, 32>>>();
    k_outbase<<<(BB * VO + 255) / 256, 256>>>(o_out);
    k_scatter<<<MM / 256, 256>>>(eidx, o_out);
    k_weighted<<<BB, 256>>>(input_idx, eidx, encoded, bin, o_w);
}

// round 17
// speedup vs baseline: 1.9225x; 1.0132x over previous
#include <cuda_runtime.h>
#include <cuda_fp16.h>
#include <math.h>
#include <stdint.h>

#define BB    32
#define SS    1024
#define VV    32000
#define EE    256
#define HH    512
#define OOV   12
#define DD2   1124
#define ININ  1380
#define MM    (BB*SS)
#define VO    (VV+OOV)
#define H3    (3*HH)

/* ------------- device scratch (no allocation allowed) ------------------ */
__device__ float g_x[BB*ININ];
__device__ float g_wsum[HH];
__device__ float g_gi[BB*H3];
__device__ float g_gh[BB*H3];
__device__ float g_state[BB*HH];
__device__ float g_score_g[BB*VV];
__device__ float g_score_c[MM];
__device__ float g_max[BB], g_Z[BB], g_Sc[BB], g_C[1];
__device__ __half g_ench[(size_t)MM*1024];   /* enc[:, :1024] in fp16 */
__device__ __half g_wch[HH*1024];            /* Wc[:, :1024] in fp16  */

/* ------------- helpers ------------------------------------------------- */
__device__ __forceinline__ float tanh_fast(float x) {
    float y;
    asm("tanh.approx.f32 %0, %1;" : "=f"(y) : "f"(x));
    return y;
}
__device__ __forceinline__ uint32_t smem_u32(const void* p) {
    uint32_t a;
    asm("{ .reg .u64 t; cvta.to.shared.u64 t, %1; cvt.u32.u64 %0, t; }"
        : "=r"(a) : "l"(p));
    return a;
}
__device__ __forceinline__ void mma_tf32(float* d, const unsigned* a,
                                         unsigned b0, unsigned b1) {
    asm volatile(
        "mma.sync.aligned.m16n8k8.row.col.f32.tf32.tf32.f32 "
        "{%0,%1,%2,%3}, {%4,%5,%6,%7}, {%8,%9}, {%0,%1,%2,%3};\n"
        : "+f"(d[0]), "+f"(d[1]), "+f"(d[2]), "+f"(d[3])
        : "r"(a[0]), "r"(a[1]), "r"(a[2]), "r"(a[3]), "r"(b0), "r"(b1));
}
__device__ __forceinline__ void mma_f16(float* d, const unsigned* a,
                                        unsigned b0, unsigned b1) {
    asm volatile(
        "mma.sync.aligned.m16n8k16.row.col.f32.f16.f16.f32 "
        "{%0,%1,%2,%3}, {%4,%5,%6,%7}, {%8,%9}, {%0,%1,%2,%3};\n"
        : "+f"(d[0]), "+f"(d[1]), "+f"(d[2]), "+f"(d[3])
        : "r"(a[0]), "r"(a[1]), "r"(a[2]), "r"(a[3]), "r"(b0), "r"(b1));
}
#define LDM_X4(r0, r1, r2, r3, addr) \
    asm volatile("ldmatrix.sync.aligned.m8n8.x4.shared.b16 {%0,%1,%2,%3}, [%4];" \
                 : "=r"(r0), "=r"(r1), "=r"(r2), "=r"(r3) : "r"(addr))

#define CPA16(dst, src) \
    asm volatile("cp.async.cg.shared.global [%0], [%1], 16;" \
                 :: "r"(dst), "l"(src) : "memory")
#define CPA_COMMIT()  asm volatile("cp.async.commit_group;" ::: "memory")
#define CPA_WAIT1()   asm volatile("cp.async.wait_group 1;" ::: "memory")
#define CPA_WAIT0()   asm volatile("cp.async.wait_group 0;" ::: "memory")

/* passA smem (fp16): 3 stages x (A 128x36 + B 128x36) uint32 */
#define PA_ROW     36
#define PA_ATILE   (128*PA_ROW)
#define PA_STAGE   (2*PA_ATILE)          /* u32 per stage: A then B */
#define PA_STAGES  3
#define PA_SMEM    (PA_STAGES*PA_STAGE*4)   /* 110592 bytes */

/* k_sg smem: 2 stages x (A 32x36 + B 128x36) floats = 46080 B */
#define SG_ROW     36
#define SG_ATILE   (32*SG_ROW)
#define SG_BTILE   (128*SG_ROW)
#define SG_STAGE   (SG_ATILE + SG_BTILE)

/* ------------- fp16 conversion: enc[:, :1024] and Wc[:, :1024] --------- */
#define CV_ENC4 ((size_t)MM*1024/4)
#define CV_WC4  (HH*1024/4)
__global__ void k_conv(const float* __restrict__ enc,
                       const float* __restrict__ Wc) {
    size_t i = (size_t)blockIdx.x * blockDim.x + threadIdx.x;
    if (i < CV_ENC4) {
        float4 v = ((const float4*)enc)[i];
        __half2* dst = (__half2*)g_ench + i * 2;
        dst[0] = __floats2half2_rn(v.x, v.y);
        dst[1] = __floats2half2_rn(v.z, v.w);
    } else if (i < CV_ENC4 + CV_WC4) {
        size_t j = i - CV_ENC4;
        int row = (int)(j >> 8), c4 = (int)(j & 255);
        float4 v = *(const float4*)(Wc + (size_t)row * DD2 + c4 * 4);
        __half2* dst = (__half2*)(g_wch + row * 1024 + c4 * 4);
        dst[0] = __floats2half2_rn(v.x, v.y);
        dst[1] = __floats2half2_rn(v.z, v.w);
    }
}

/* ------------- prep: x=[emb|weighted], wsum, zero score_c -------------- */
__global__ void k_prep(const int* __restrict__ input_idx,
                       const float* __restrict__ embed,
                       const float* __restrict__ weighted,
                       const float* __restrict__ Wc) {
    int i = blockIdx.x * blockDim.x + threadIdx.x;
    if (i < BB * ININ) {
        int b = i / ININ, j = i - b * ININ;
        g_x[i] = (j < EE) ? embed[input_idx[b] * EE + j]
                          : weighted[b * DD2 + (j - EE)];
    } else if (i < BB * ININ + HH) {
        int h = i - BB * ININ;
        float s = 0.f;
        #pragma unroll 4
        for (int j = 0; j < 100; j++) s += Wc[h * DD2 + 2 * HH + j];
        g_wsum[h] = s;
    } else if (i < BB * ININ + HH + MM) {
        g_score_c[i - BB * ININ - HH] = 0.f;
    }
}

/* ------------- generic small-N SIMT GEMM core -------------------------- */
template<int RP>
__device__ __forceinline__ void gemm_core(float (*Ws)[33], float (*Xs)[33], int r0,
                                          const float* __restrict__ W, int ldw,
                                          const float* __restrict__ X, int ldx,
                                          const float* __restrict__ bias,
                                          float* __restrict__ out, int ldo, int K) {
    const int tid = threadIdx.x;
    const int vi  = tid & 31, bi = tid >> 5;
    float acc[RP][4];
    #pragma unroll
    for (int p = 0; p < RP; p++)
        #pragma unroll
        for (int q = 0; q < 4; q++) acc[p][q] = 0.f;

    for (int kc = 0; kc < K; kc += 32) {
        for (int e = tid; e < RP * 32 * 32; e += 256) {
            int row = e >> 5, k = e & 31;
            Ws[row][k] = (kc + k < K) ? W[(r0 + row) * ldw + kc + k] : 0.f;
        }
        for (int e = tid; e < 32 * 32; e += 256) {
            int row = e >> 5, k = e & 31;
            Xs[row][k] = (kc + k < K) ? X[row * ldx + kc + k] : 0.f;
        }
        __syncthreads();
        #pragma unroll
        for (int k = 0; k < 32; k++) {
            float x[4];
            #pragma unroll
            for (int q = 0; q < 4; q++) x[q] = Xs[bi * 4 + q][k];
            #pragma unroll
            for (int p = 0; p < RP; p++) {
                float w = Ws[vi + 32 * p][k];
                #pragma unroll
                for (int q = 0; q < 4; q++) acc[p][q] += w * x[q];
            }
        }
        __syncthreads();
    }
    #pragma unroll
    for (int p = 0; p < RP; p++) {
        int r = r0 + vi + 32 * p;
        float bv = bias[r];
        #pragma unroll
        for (int q = 0; q < 4; q++)
            out[(bi * 4 + q) * ldo + r] = acc[p][q] + bv;
    }
}

/* merged GRU input/hidden GEMMs */
__global__ void __launch_bounds__(256) k_gru(const float* __restrict__ W_ih,
                                             const float* __restrict__ b_ih,
                                             const float* __restrict__ W_hh,
                                             const float* __restrict__ b_hh,
                                             const float* __restrict__ prev) {
    __shared__ float Ws[64][33]; __shared__ float Xs[32][33];
    if (blockIdx.x < 24)
        gemm_core<2>(Ws, Xs, blockIdx.x * 64, W_ih, ININ, g_x, ININ, b_ih, g_gi, H3, ININ);
    else
        gemm_core<2>(Ws, Xs, (blockIdx.x - 24) * 64, W_hh, HH, prev, HH, b_hh, g_gh, H3, HH);
}

/* ------------- score_g: tf32 mma streaming GEMM ------------------------ */
__device__ __forceinline__ void sg_load(float* sm, int stage, int chunk,
                                        const float* __restrict__ W,
                                        int n0, int tid) {
    float* As = sm + stage * SG_STAGE;
    float* Bs = As + SG_ATILE;
    const uint32_t a_u = smem_u32(As);
    const uint32_t b_u = smem_u32(Bs);
    const int kc = chunk * 32;
    {
        int row = tid >> 3, q = tid & 7;
        CPA16(a_u + (uint32_t)(row * SG_ROW + q * 4) * 4,
              g_state + row * HH + kc + q * 4);
    }
    #pragma unroll
    for (int j = 0; j < 4; j++) {
        int u = tid + j * 256;
        int row = u >> 3, q = u & 7;
        CPA16(b_u + (uint32_t)(row * SG_ROW + q * 4) * 4,
              W + (size_t)(n0 + row) * HH + kc + q * 4);
    }
    CPA_COMMIT();
}

__global__ void __launch_bounds__(256, 2) k_sg(const float* __restrict__ W,
                                               const float* __restrict__ bias) {
    __shared__ __align__(16) float sm[2 * SG_STAGE];
    const int tid  = threadIdx.x;
    const int lane = tid & 31, warp = tid >> 5;
    const int gid  = lane >> 2, tig = lane & 3;
    const int n0   = blockIdx.x * 128;

    float acc[2][2][4];
    #pragma unroll
    for (int a = 0; a < 2; a++)
        #pragma unroll
        for (int b = 0; b < 2; b++)
            #pragma unroll
            for (int c = 0; c < 4; c++) acc[a][b][c] = 0.f;

    sg_load(sm, 0, 0, W, n0, tid);
    sg_load(sm, 1, 1, W, n0, tid);

    for (int kt = 0; kt < 16; kt++) {
        const int s = kt & 1;
        if (kt < 15) { CPA_WAIT1(); } else { CPA_WAIT0(); }
        __syncthreads();

        const float* As = sm + s * SG_STAGE;
        const float* Bs = As + SG_ATILE;
        #pragma unroll
        for (int ks = 0; ks < 4; ks++) {
            const int kb = ks * 8;
            unsigned af[2][4];
            #pragma unroll
            for (int mt = 0; mt < 2; mt++) {
                int r = mt * 16 + gid;
                af[mt][0] = __float_as_uint(As[r * SG_ROW + kb + tig]);
                af[mt][1] = __float_as_uint(As[(r + 8) * SG_ROW + kb + tig]);
                af[mt][2] = __float_as_uint(As[r * SG_ROW + kb + tig + 4]);
                af[mt][3] = __float_as_uint(As[(r + 8) * SG_ROW + kb + tig + 4]);
            }
            #pragma unroll
            for (int nt = 0; nt < 2; nt++) {
                int c = warp * 16 + nt * 8 + gid;
                unsigned b0 = __float_as_uint(Bs[c * SG_ROW + kb + tig]);
                unsigned b1 = __float_as_uint(Bs[c * SG_ROW + kb + tig + 4]);
                mma_tf32(acc[0][nt], af[0], b0, b1);
                mma_tf32(acc[1][nt], af[1], b0, b1);
            }
        }
        __syncthreads();
        if (kt + 2 < 16)
            sg_load(sm, s, kt + 2, W, n0, tid);
    }

    #pragma unroll
    for (int mt = 0; mt < 2; mt++) {
        #pragma unroll
        for (int nt = 0; nt < 2; nt++) {
            int br = mt * 16 + gid;
            int c  = n0 + warp * 16 + nt * 8 + tig * 2;
            float bi0 = bias[c], bi1 = bias[c + 1];
            g_score_g[br * VV + c]           = acc[mt][nt][0] + bi0;
            g_score_g[br * VV + c + 1]       = acc[mt][nt][1] + bi1;
            g_score_g[(br + 8) * VV + c]     = acc[mt][nt][2] + bi0;
            g_score_g[(br + 8) * VV + c + 1] = acc[mt][nt][3] + bi1;
        }
    }
}

/* ------------- GRU gate combine ---------------------------------------- */
__global__ void k_gates(const float* __restrict__ prev, float* __restrict__ o_state) {
    int idx = blockIdx.x * blockDim.x + threadIdx.x;
    if (idx >= BB * HH) return;
    int b = idx >> 9, h = idx & (HH - 1);
    const float* gi = g_gi + b * H3;
    const float* gh = g_gh + b * H3;
    float r  = 1.f / (1.f + expf(-(gi[h] + gh[h])));
    float z  = 1.f / (1.f + expf(-(gi[HH + h] + gh[HH + h])));
    float nn = tanhf(gi[2 * HH + h] + r * gh[2 * HH + h]);
    float st = (1.f - z) * nn + z * prev[idx];
    g_state[idx] = st;
    o_state[idx] = st;
}

/* ------------- pass A: fp16 m16n8k16 mma + ldmatrix, 3-stage pipeline --- */
__device__ __forceinline__ void pa_load(uint32_t* sm, int slot, int chunk,
                                        int m0, int n0, int tid) {
    uint32_t* As = sm + slot * PA_STAGE;
    uint32_t* Bs = As + PA_ATILE;
    const uint32_t a_u32 = smem_u32(As);
    const uint32_t b_u32 = smem_u32(Bs);
    const int kc = chunk * 64;           /* halves */
    #pragma unroll
    for (int j = 0; j < 4; j++) {
        int u = tid + j * 256;
        int row = u >> 3, q = u & 7;
        CPA16(a_u32 + (uint32_t)(row * PA_ROW + q * 4) * 4,
              g_ench + (size_t)(m0 + row) * 1024 + kc + q * 8);
        CPA16(b_u32 + (uint32_t)(row * PA_ROW + q * 4) * 4,
              g_wch + (size_t)(n0 + row) * 1024 + kc + q * 8);
    }
    CPA_COMMIT();
}

__global__ void __launch_bounds__(256, 2) k_passA(const float* __restrict__ Wcb,
                                                  const float* __restrict__ bin) {
    extern __shared__ __align__(16) uint32_t smu[];
    const int tid  = threadIdx.x;
    const int lane = tid & 31, warp = tid >> 5;
    const int gid  = lane >> 2, tig = lane & 3;
    const int wm   = warp & 3, wn = warp >> 2;        /* 4 x 2 warps */
    const int m0   = blockIdx.y * 128;
    const int n0   = blockIdx.x * 128;

    const uint32_t smb = smem_u32(smu);
    const int lrow8 = lane & 7;
    const int quad  = lane >> 3;

    uint32_t aStat[2];
    #pragma unroll
    for (int mt = 0; mt < 2; mt++) {
        int aRow  = wm * 32 + mt * 16 + (quad & 1) * 8 + lrow8;
        int aColU = (quad >> 1) * 4;
        aStat[mt] = (uint32_t)(aRow * PA_ROW + aColU) * 4;
    }
    uint32_t bStat[4];
    #pragma unroll
    for (int g = 0; g < 4; g++) {
        int bRow  = wn * 64 + (2 * g + (quad >> 1)) * 8 + lrow8;
        int bColU = (quad & 1) * 4;
        bStat[g] = (uint32_t)(PA_ATILE * 4) + (uint32_t)(bRow * PA_ROW + bColU) * 4;
    }

    float acc[2][8][4];
    #pragma unroll
    for (int a = 0; a < 2; a++)
        #pragma unroll
        for (int b = 0; b < 8; b++)
            #pragma unroll
            for (int c = 0; c < 4; c++) acc[a][b][c] = 0.f;

    pa_load(smu, 0, 0, m0, n0, tid);
    pa_load(smu, 1, 1, m0, n0, tid);

    int slot = 0, nslot = 2;
    for (int kt = 0; kt < 16; kt++) {
        if (kt < 15) { CPA_WAIT1(); } else { CPA_WAIT0(); }
        __syncthreads();

        /* issue next load first: slot (kt+2)%3 == (kt-1)%3, safe after sync */
        if (kt + 2 < 16) {
            pa_load(smu, nslot, kt + 2, m0, n0, tid);
        }

        const uint32_t stageBase = smb + (uint32_t)(slot * PA_STAGE) * 4;
        #pragma unroll
        for (int ks = 0; ks < 4; ks++) {
            const uint32_t kOff = (uint32_t)(ks * 8) * 4;
            unsigned af[2][4];
            LDM_X4(af[0][0], af[0][1], af[0][2], af[0][3], stageBase + aStat[0] + kOff);
            LDM_X4(af[1][0], af[1][1], af[1][2], af[1][3], stageBase + aStat[1] + kOff);
            unsigned bfr[16];
            LDM_X4(bfr[0],  bfr[1],  bfr[2],  bfr[3],  stageBase + bStat[0] + kOff);
            LDM_X4(bfr[4],  bfr[5],  bfr[6],  bfr[7],  stageBase + bStat[1] + kOff);
            LDM_X4(bfr[8],  bfr[9],  bfr[10], bfr[11], stageBase + bStat[2] + kOff);
            LDM_X4(bfr[12], bfr[13], bfr[14], bfr[15], stageBase + bStat[3] + kOff);
            #pragma unroll
            for (int nt = 0; nt < 8; nt++) {
                mma_f16(acc[0][nt], af[0], bfr[2 * nt], bfr[2 * nt + 1]);
                mma_f16(acc[1][nt], af[1], bfr[2 * nt], bfr[2 * nt + 1]);
            }
        }
        slot  = (slot == 2)  ? 0 : slot + 1;
        nslot = (nslot == 2) ? 0 : nslot + 1;
    }

    /* epilogue: rank-1 + bias, tanh, multiply by state, reduce over h */
    const int bidx = m0 >> 10;
    const float* st = g_state + bidx * HH;
    #pragma unroll
    for (int mt = 0; mt < 2; mt++) {
        int rg = m0 + wm * 32 + mt * 16 + gid;
        float b0v = bin[rg], b1v = bin[rg + 8];
        float p0 = 0.f, p1 = 0.f;
        #pragma unroll
        for (int nt = 0; nt < 8; nt++) {
            int c0 = n0 + wn * 64 + nt * 8 + tig * 2;
            float ws0 = g_wsum[c0], ws1 = g_wsum[c0 + 1];
            float bb0 = Wcb[c0],    bb1 = Wcb[c0 + 1];
            float s0  = st[c0],     s1  = st[c0 + 1];
            p0 += tanh_fast(acc[mt][nt][0] + b0v * ws0 + bb0) * s0
                + tanh_fast(acc[mt][nt][1] + b0v * ws1 + bb1) * s1;
            p1 += tanh_fast(acc[mt][nt][2] + b1v * ws0 + bb0) * s0
                + tanh_fast(acc[mt][nt][3] + b1v * ws1 + bb1) * s1;
        }
        p0 += __shfl_xor_sync(0xffffffffu, p0, 1);
        p0 += __shfl_xor_sync(0xffffffffu, p0, 2);
        p1 += __shfl_xor_sync(0xffffffffu, p1, 1);
        p1 += __shfl_xor_sync(0xffffffffu, p1, 2);
        if (tig == 0) {
            atomicAdd(&g_score_c[rg], p0);
            atomicAdd(&g_score_c[rg + 8], p1);
        }
    }
}

/* ------------- finalize score_c: tanh + mask --------------------------- */
__global__ void k_fin(const int* __restrict__ eidx) {
    int m = blockIdx.x * blockDim.x + threadIdx.x;
    if (m >= MM) return;
    float v = tanhf(g_score_c[m]);
    if (eidx[m] == 0) v -= 1000.f;
    g_score_c[m] = v;
}

/* ------------- per-row softmax stats (1024 threads) --------------------- */
__global__ void __launch_bounds__(1024) k_rowstats() {
    __shared__ float red[1024];
    const int b = blockIdx.x, tid = threadIdx.x;
    const float* sg = g_score_g + b * VV;
    const float* sc = g_score_c + b * SS;
    float mx = -1e30f;
    for (int i = tid; i < VV; i += 1024) mx = fmaxf(mx, sg[i]);
    for (int i = tid; i < SS; i += 1024) mx = fmaxf(mx, sc[i]);
    red[tid] = mx; __syncthreads();
    for (int o = 512; o; o >>= 1) { if (tid < o) red[tid] = fmaxf(red[tid], red[tid + o]); __syncthreads(); }
    mx = red[0]; __syncthreads();

    float zg = 0.f;
    for (int i = tid; i < VV; i += 1024) zg += expf(sg[i] - mx);
    float zc = 0.f;
    for (int i = tid; i < SS; i += 1024) zc += expf(sc[i] - mx);
    red[tid] = zg + zc; __syncthreads();
    for (int o = 512; o; o >>= 1) { if (tid < o) red[tid] += red[tid + o]; __syncthreads(); }
    float Z = red[0]; __syncthreads();
    red[tid] = zc; __syncthreads();
    for (int o = 512; o; o >>= 1) { if (tid < o) red[tid] += red[tid + o]; __syncthreads(); }
    if (tid == 0) { g_max[b] = mx; g_Z[b] = Z; g_Sc[b] = red[0]; }
}

__global__ void k_compC() {
    int t = threadIdx.x;
    float v = (t < BB) ? g_Sc[t] / g_Z[t] : 0.f;
    #pragma unroll
    for (int o = 16; o; o >>= 1) v += __shfl_xor_sync(0xffffffffu, v, o);
    if (t == 0) g_C[0] = v;
}

/* ------------- output: base probs -------------------------------------- */
__global__ void k_outbase(float* __restrict__ o_out) {
    int i = blockIdx.x * blockDim.x + threadIdx.x;
    if (i >= BB * VO) return;
    int b = i / VO, v = i - b * VO;
    o_out[i] = (v < VV) ? expf(g_score_g[b * VV + v] - g_max[b]) / g_Z[b] : 1e-4f;
}

/* ------------- output: scatter-add prob_c ------------------------------- */
__global__ void k_scatter(const int* __restrict__ eidx, float* __restrict__ o_out) {
    int m = blockIdx.x * blockDim.x + threadIdx.x;
    if (m >= MM) return;
    int b = m >> 10;
    float p = expf(g_score_c[m] - g_max[b]) / g_Z[b];
    atomicAdd(o_out + b * VO + eidx[m], p);
}

/* ------------- weighted_out (sparse attn over idx matches) -------------- */
__global__ void k_weighted(const int* __restrict__ input_idx,
                           const int* __restrict__ eidx,
                           const float* __restrict__ encoded,
                           const float* __restrict__ bin,
                           float* __restrict__ o_w) {
    __shared__ int cnt;
    __shared__ int sl[SS];
    __shared__ float av[SS];
    const int b = blockIdx.x, tid = threadIdx.x;
    if (tid == 0) cnt = 0;
    __syncthreads();
    int target = input_idx[b];
    for (int s = tid; s < SS; s += 256)
        if (eidx[b * SS + s] == target) { int p = atomicAdd(&cnt, 1); sl[p] = s; }
    __syncthreads();
    int n = cnt;
    float scale = (n > 1) ? 1.f / (float)n : 1.f;
    for (int i = tid; i < n; i += 256) {
        int s = sl[i];
        float pc = expf(g_score_c[b * SS + s] - g_max[b]) / g_Z[b];
        av[i] = pc / g_C[0] * scale;
    }
    __syncthreads();
    for (int d = tid; d < DD2; d += 256) {
        float acc = 0.f;
        for (int i = 0; i < n; i++) {
            int s = sl[i];
            float e = (d < 2 * HH) ? encoded[(size_t)(b * SS + s) * (2 * HH) + d]
                                   : bin[b * SS + s];
            acc += av[i] * e;
        }
        o_w[b * DD2 + d] = acc;
    }
}

/* ======================= host launcher ================================== */
extern "C" void kernel_launch(void* const* d_in, const int* in_sizes, int n_in,
                              void* d_out, int out_size) {
    const int*   input_idx = (const int*)  d_in[0];
    const float* encoded   = (const float*)d_in[1];
    const int*   eidx      = (const int*)  d_in[2];
    const float* prev      = (const float*)d_in[3];
    const float* weighted  = (const float*)d_in[4];
    const float* bin       = (const float*)d_in[5];
    /* d_in[6] = order (always 1) */
    const float* embed     = (const float*)d_in[7];
    const float* W_ih      = (const float*)d_in[8];
    const float* b_ih      = (const float*)d_in[9];
    const float* W_hh      = (const float*)d_in[10];
    const float* b_hh      = (const float*)d_in[11];
    const float* Wo_w      = (const float*)d_in[12];
    const float* Wo_b      = (const float*)d_in[13];
    const float* Wc_w      = (const float*)d_in[14];
    const float* Wc_b      = (const float*)d_in[15];

    float* o_out   = (float*)d_out;
    float* o_state = o_out + (size_t)BB * VO;
    float* o_w     = o_state + (size_t)BB * HH;

    static cudaStream_t s2 = 0;
    static cudaEvent_t eFork = 0, eConv = 0, eGates = 0, eSg = 0;
    if (!s2) {
        cudaStreamCreateWithFlags(&s2, cudaStreamNonBlocking);
        cudaEventCreateWithFlags(&eFork,  cudaEventDisableTiming);
        cudaEventCreateWithFlags(&eConv,  cudaEventDisableTiming);
        cudaEventCreateWithFlags(&eGates, cudaEventDisableTiming);
        cudaEventCreateWithFlags(&eSg,    cudaEventDisableTiming);
        cudaFuncSetAttribute(k_passA, cudaFuncAttributeMaxDynamicSharedMemorySize,
                             PA_SMEM);
    }

    /* fork: conversion stream */
    cudaEventRecord(eFork, 0);
    cudaStreamWaitEvent(s2, eFork, 0);
    {
        size_t tot = CV_ENC4 + CV_WC4;
        k_conv<<<(unsigned)((tot + 255) / 256), 256, 0, s2>>>(encoded, Wc_w);
    }
    cudaEventRecord(eConv, s2);

    /* main: GRU chain */
    int prep_n = BB * ININ + HH + MM;
    k_prep<<<(prep_n + 255) / 256, 256>>>(input_idx, embed, weighted, Wc_w);
    k_gru<<<48, 256>>>(W_ih, b_ih, W_hh, b_hh, prev);
    k_gates<<<(BB * HH + 255) / 256, 256>>>(prev, o_state);
    cudaEventRecord(eGates, 0);

    /* s2: score_g GEMM (needs g_state) runs concurrent with passA */
    cudaStreamWaitEvent(s2, eGates, 0);
    k_sg<<<VV / 128, 256, 0, s2>>>(Wo_w, Wo_b);
    cudaEventRecord(eSg, s2);

    /* main: passA (needs conversion) */
    cudaStreamWaitEvent(0, eConv, 0);
    {
        dim3 grid(HH / 128, MM / 128);   /* n fastest */
        k_passA<<<grid, 256, PA_SMEM>>>(Wc_b, bin);
    }
    k_fin<<<MM / 256, 256>>>(eidx);

    /* join: rowstats needs score_g (s2) and score_c (main) */
    cudaStreamWaitEvent(0, eSg, 0);
    k_rowstats<<<BB, 1024>>>();
    k_compC<<<1, 32>>>();
    k_outbase<<<(BB * VO + 255) / 256, 256>>>(o_out);
    k_scatter<<<MM / 256, 256>>>(eidx, o_out);
    k_weighted<<<BB, 256>>>(input_idx, eidx, encoded, bin, o_w);
}